// round 13
// baseline (speedup 1.0000x reference)
#include <cuda_runtime.h>
#include <cuda_bf16.h>
#include <math.h>
#include <stdint.h>

typedef __nv_bfloat16 bf16;

// ---------------- problem constants ----------------
constexpr int TB = 4;
constexpr int TN = 1025;
constexpr int TL = 1024;
constexpr int TE = 1024;
constexpr int TH = 16;
constexpr int TD = 64;
constexpr int TF = 4096;
constexpr int TM = TB * TN;           // 4100
constexpr float ATT_SCALE = 0.125f;

// flash smem
constexpr int FTILE = 128 * 72;
constexpr int SMEM_FLASH = 5 * FTILE * 2 + 63 * 64 * 4;   // 108288 bytes

// gemm smem: 3 stages of (A 128x40 + B 128x40) bf16
constexpr int GSTAGE = (128 + 128) * 40;                  // halfwords per stage
constexpr int SMEM_GEMM = 3 * GSTAGE * 2;                 // 61440 bytes

// ---------------- scratch ----------------
__device__ bf16  g_hb  [(size_t)TM * TE];
__device__ bf16  g_yb  [(size_t)TB * TL * TE];
__device__ bf16  g_qkvb[(size_t)TM * 3 * TE];
__device__ bf16  g_kvb [(size_t)TB * TL * 2 * TE];
__device__ bf16  g_q2b [(size_t)TM * TE];
__device__ bf16  g_attnb[(size_t)TM * TE];
__device__ bf16  g_ffnb[(size_t)TM * TF];
__device__ bf16  g_wqkv[(size_t)3 * TE * TE];
__device__ bf16  g_wkv [(size_t)2 * TE * TE];
__device__ bf16  g_wq  [(size_t)TE * TE];
__device__ bf16  g_wp1 [(size_t)TE * TE];
__device__ bf16  g_wp2 [(size_t)TE * TE];
__device__ bf16  g_wf1 [(size_t)TF * TE];
__device__ bf16  g_wf2 [(size_t)TE * TF];
__device__ float g_bias3[3 * TE];
__device__ float g_bias2[2 * TE];

// ---------------- PTX helpers ----------------
__device__ __forceinline__ void cp16(uint32_t smem, const void* gmem, int bytes) {
    asm volatile("cp.async.cg.shared.global [%0], [%1], 16, %2;\n"
                 :: "r"(smem), "l"(gmem), "r"(bytes));
}
__device__ __forceinline__ void cp_commit() { asm volatile("cp.async.commit_group;\n"); }

__device__ __forceinline__ void ldmA(uint32_t* a, uint32_t addr) {
    asm volatile("ldmatrix.sync.aligned.m8n8.x4.shared.b16 {%0,%1,%2,%3}, [%4];\n"
                 : "=r"(a[0]), "=r"(a[1]), "=r"(a[2]), "=r"(a[3]) : "r"(addr));
}
__device__ __forceinline__ void ldmT4(uint32_t* b, uint32_t addr) {
    asm volatile("ldmatrix.sync.aligned.m8n8.x4.trans.shared.b16 {%0,%1,%2,%3}, [%4];\n"
                 : "=r"(b[0]), "=r"(b[1]), "=r"(b[2]), "=r"(b[3]) : "r"(addr));
}
__device__ __forceinline__ void mma_bf16(float* d, const uint32_t* a, const uint32_t* b) {
    asm volatile("mma.sync.aligned.m16n8k16.row.col.f32.bf16.bf16.f32 "
                 "{%0,%1,%2,%3}, {%4,%5,%6,%7}, {%8,%9}, {%0,%1,%2,%3};\n"
                 : "+f"(d[0]), "+f"(d[1]), "+f"(d[2]), "+f"(d[3])
                 : "r"(a[0]), "r"(a[1]), "r"(a[2]), "r"(a[3]), "r"(b[0]), "r"(b[1]));
}
__device__ __forceinline__ uint32_t packbf(float x, float y) {
    __nv_bfloat162 p = __floats2bfloat162_rn(x, y);
    return *(uint32_t*)&p;
}

// ---------------- reductions ----------------
__device__ __forceinline__ float block_sum(float v) {
    __shared__ float sm[32];
    int lane = threadIdx.x & 31, wid = threadIdx.x >> 5;
#pragma unroll
    for (int o = 16; o > 0; o >>= 1) v += __shfl_xor_sync(0xffffffffu, v, o);
    if (lane == 0) sm[wid] = v;
    __syncthreads();
    if (wid == 0) {
        v = (lane < (int)(blockDim.x >> 5)) ? sm[lane] : 0.f;
#pragma unroll
        for (int o = 16; o > 0; o >>= 1) v += __shfl_xor_sync(0xffffffffu, v, o);
        if (lane == 0) sm[0] = v;
    }
    __syncthreads();
    float r = sm[0];
    __syncthreads();
    return r;
}

// ---------------- fused fp32->bf16 conversion for all weights + y ----------------
__global__ void f2bf_all(const float* __restrict__ s0, const float* __restrict__ s1,
                         const float* __restrict__ s2, const float* __restrict__ s3,
                         const float* __restrict__ s4, const float* __restrict__ s5,
                         const float* __restrict__ s6, const float* __restrict__ s7,
                         bf16* d0, bf16* d1, bf16* d2, bf16* d3,
                         bf16* d4, bf16* d5, bf16* d6, bf16* d7) {
    long i = (long)blockIdx.x * 256 + threadIdx.x;   // vec4 index
    const float* s; bf16* d;
    if (i < 786432)                    { s = s0; d = d0; }
    else if ((i -= 786432) < 524288)   { s = s1; d = d1; }
    else if ((i -= 524288) < 262144)   { s = s2; d = d2; }
    else if ((i -= 262144) < 262144)   { s = s3; d = d3; }
    else if ((i -= 262144) < 262144)   { s = s4; d = d4; }
    else if ((i -= 262144) < 1048576)  { s = s5; d = d5; }
    else if ((i -= 1048576) < 1048576) { s = s6; d = d6; }
    else { i -= 1048576;                 s = s7; d = d7; }
    float4 v = ((const float4*)s)[i];
    __nv_bfloat162 p0, p1;
    p0.x = __float2bfloat16(v.x); p0.y = __float2bfloat16(v.y);
    p1.x = __float2bfloat16(v.z); p1.y = __float2bfloat16(v.w);
    __nv_bfloat162* o = (__nv_bfloat162*)(d + i * 4);
    o[0] = p0; o[1] = p1;
}

__global__ void build_bias_kernel(const float* __restrict__ saq,
                                  const float* __restrict__ sav,
                                  const float* __restrict__ cav) {
    int i = blockIdx.x * 256 + threadIdx.x;
    if (i < 3 * TE)
        g_bias3[i] = (i < TE) ? saq[i] : ((i < 2 * TE) ? 0.f : sav[i - 2 * TE]);
    if (i < 2 * TE)
        g_bias2[i] = (i < TE) ? 0.f : cav[i - TE];
}

// LayerNorm: fp32 in -> bf16 out
__global__ void ln_kernel(const float* __restrict__ x, const float* __restrict__ g,
                          const float* __restrict__ b, bf16* __restrict__ out) {
    int row = blockIdx.x;
    int t = threadIdx.x;
    float4 v = ((const float4*)(x + (size_t)row * TE))[t];
    float mean = block_sum(v.x + v.y + v.z + v.w) * (1.f / TE);
    float dx = v.x - mean, dy = v.y - mean, dz = v.z - mean, dw = v.w - mean;
    float var = block_sum(dx * dx + dy * dy + dz * dz + dw * dw) * (1.f / TE);
    float rstd = rsqrtf(var + 1e-5f);
    float4 gg = ((const float4*)g)[t];
    float4 bb = ((const float4*)b)[t];
    __nv_bfloat162 p0, p1;
    p0.x = __float2bfloat16(dx * rstd * gg.x + bb.x);
    p0.y = __float2bfloat16(dy * rstd * gg.y + bb.y);
    p1.x = __float2bfloat16(dz * rstd * gg.z + bb.z);
    p1.y = __float2bfloat16(dw * rstd * gg.w + bb.w);
    __nv_bfloat162* o = (__nv_bfloat162*)(out + (size_t)row * TE);
    o[2 * t] = p0; o[2 * t + 1] = p1;
}

// ---------------- bf16 tensor-core GEMM (128x128 tile, 3-stage, x4 B-frags) ----------------
template<int EPI>
__global__ void __launch_bounds__(256)
bgemm(const bf16* __restrict__ A, int lda,
      const bf16* __restrict__ W,
      int M, int Ncols, int K,
      const float* __restrict__ bias,
      const float* __restrict__ res,
      const float* __restrict__ gamma,
      float* __restrict__ Cf, bf16* __restrict__ Cb, int ldc) {
    extern __shared__ bf16 smg[];
    const int t = threadIdx.x, lane = t & 31, wid = t >> 5;
    const int m0 = blockIdx.y * 128, n0 = blockIdx.x * 128;
    uint32_t sAb[3], sBb[3];
#pragma unroll
    for (int s = 0; s < 3; s++) {
        sAb[s] = (uint32_t)__cvta_generic_to_shared(smg + s * GSTAGE);
        sBb[s] = sAb[s] + 128 * 40 * 2;
    }

    auto load_stage = [&](int s) {
        int k0 = s * 32, buf = s % 3;
#pragma unroll
        for (int i = 0; i < 2; i++) {
            int c = t + i * 256; int row = c >> 2; int cc = c & 3;
            bool v = (m0 + row) < M;
            const bf16* src = A + (size_t)(v ? m0 + row : 0) * lda + k0 + cc * 8;
            cp16(sAb[buf] + (row * 40 + cc * 8) * 2, src, v ? 16 : 0);
        }
#pragma unroll
        for (int i = 0; i < 2; i++) {
            int c = t + i * 256; int row = c >> 2; int cc = c & 3;
            bool v = (n0 + row) < Ncols;
            const bf16* src = W + (size_t)(v ? n0 + row : 0) * K + k0 + cc * 8;
            cp16(sBb[buf] + (row * 40 + cc * 8) * 2, src, v ? 16 : 0);
        }
        cp_commit();
    };

    const int wm = (wid >> 2) * 64, wn = (wid & 3) * 32;
    float acc[4][4][4] = {};
    const int NS = K / 32;
    load_stage(0);
    if (NS > 1) load_stage(1);
    for (int s = 0; s < NS; s++) {
        if (s + 1 < NS) asm volatile("cp.async.wait_group 1;\n");
        else            asm volatile("cp.async.wait_group 0;\n");
        __syncthreads();
        int buf = s % 3;
#pragma unroll
        for (int ks = 0; ks < 2; ks++) {
            uint32_t af[4][4];
#pragma unroll
            for (int mt = 0; mt < 4; mt++)
                ldmA(af[mt], sAb[buf] + ((wm + mt * 16 + (lane & 15)) * 40 + ks * 16 + (lane >> 4) * 8) * 2);
            uint32_t bfr[4][2];
#pragma unroll
            for (int np = 0; np < 2; np++) {
                uint32_t kf[4];
                ldmA(kf, sBb[buf] + ((wn + np * 16 + (lane & 15)) * 40 + ks * 16 + (lane >> 4) * 8) * 2);
                bfr[2 * np][0] = kf[0]; bfr[2 * np][1] = kf[2];
                bfr[2 * np + 1][0] = kf[1]; bfr[2 * np + 1][1] = kf[3];
            }
#pragma unroll
            for (int mt = 0; mt < 4; mt++)
#pragma unroll
                for (int nt = 0; nt < 4; nt++) mma_bf16(acc[mt][nt], af[mt], bfr[nt]);
        }
        if (s + 2 < NS) load_stage(s + 2);
    }

#pragma unroll
    for (int mt = 0; mt < 4; mt++)
#pragma unroll
        for (int nt = 0; nt < 4; nt++) {
            int col = n0 + wn + nt * 8 + (lane & 3) * 2;
            float b0 = bias[col], b1 = bias[col + 1];
#pragma unroll
            for (int h2 = 0; h2 < 2; h2++) {
                int gm = m0 + wm + mt * 16 + (lane >> 2) + h2 * 8;
                if (gm >= M) continue;
                float v0 = acc[mt][nt][h2 * 2 + 0] + b0;
                float v1 = acc[mt][nt][h2 * 2 + 1] + b1;
                if (EPI == 1) {
                    v0 = 0.5f * v0 * (1.f + erff(v0 * 0.70710678118654752f));
                    v1 = 0.5f * v1 * (1.f + erff(v1 * 0.70710678118654752f));
                }
                if (EPI == 2) {
                    float2 r = *(const float2*)(res + (size_t)gm * ldc + col);
                    v0 = r.x + gamma[col] * v0;
                    v1 = r.y + gamma[col + 1] * v1;
                    *(float2*)(Cf + (size_t)gm * ldc + col) = make_float2(v0, v1);
                } else {
                    __nv_bfloat162 o;
                    o.x = __float2bfloat16(v0); o.y = __float2bfloat16(v1);
                    *(__nv_bfloat162*)(Cb + (size_t)gm * ldc + col) = o;
                }
            }
        }
}

// ---------------- fused flash attention (self: heavy q-tiles first) ----------------
template<bool SELF>
__global__ void __launch_bounds__(256)
flash_attn(const bf16* __restrict__ qsrc, const bf16* __restrict__ kvsrc,
           const float* __restrict__ rpb, bf16* __restrict__ outp) {
    extern __shared__ char dsm[];
    bf16* Qs = (bf16*)dsm;
    bf16* Ks = Qs + FTILE;
    bf16* Vs = Ks + 2 * FTILE;
    float* tab = (float*)(dsm + 5 * FTILE * 2);

    const int t = threadIdx.x, lane = t & 31, wid = t >> 5;
    const int b = blockIdx.z >> 4, h = blockIdx.z & 15;
    const int qt = SELF ? (8 - (int)blockIdx.x) : (int)blockIdx.x;
    const int q0 = qt * 128;
    const int Nk = SELF ? TN : TL;
    const int nkt = SELF ? (qt + 1) : 8;
    const int ldq = SELF ? 3 * TE : TE;
    const int ldk = SELF ? 3 * TE : 2 * TE;
    const bf16* qp = SELF ? qsrc + (size_t)b * TN * 3 * TE + h * TD
                          : qsrc + (size_t)b * TN * TE + h * TD;
    const bf16* kp = SELF ? kvsrc + (size_t)b * TN * 3 * TE + TE + h * TD
                          : kvsrc + (size_t)b * TL * 2 * TE + h * TD;
    const bf16* vp = SELF ? kvsrc + (size_t)b * TN * 3 * TE + 2 * TE + h * TD
                          : kvsrc + (size_t)b * TL * 2 * TE + TE + h * TD;

    uint32_t Qb = (uint32_t)__cvta_generic_to_shared(Qs);
    uint32_t Kb[2] = {(uint32_t)__cvta_generic_to_shared(Ks),
                      (uint32_t)__cvta_generic_to_shared(Ks + FTILE)};
    uint32_t Vb[2] = {(uint32_t)__cvta_generic_to_shared(Vs),
                      (uint32_t)__cvta_generic_to_shared(Vs + FTILE)};

#pragma unroll
    for (int i = 0; i < 4; i++) {
        int c = t + i * 256; int row = c >> 3; int cc = c & 7;
        bool v = (q0 + row) < TN;
        cp16(Qb + (row * 72 + cc * 8) * 2, qp + (size_t)(v ? q0 + row : 0) * ldq + cc * 8, v ? 16 : 0);
    }
    auto load_kv = [&](int kt) {
        int buf = kt & 1;
#pragma unroll
        for (int i = 0; i < 4; i++) {
            int c = t + i * 256; int row = c >> 3; int cc = c & 7;
            int gk = kt * 128 + row;
            bool v = gk < Nk;
            const bf16* ksrc2 = kp + (size_t)(v ? gk : 0) * ldk + cc * 8;
            const bf16* vsrc2 = vp + (size_t)(v ? gk : 0) * ldk + cc * 8;
            cp16(Kb[buf] + (row * 72 + cc * 8) * 2, ksrc2, v ? 16 : 0);
            cp16(Vb[buf] + (row * 72 + cc * 8) * 2, vsrc2, v ? 16 : 0);
        }
        cp_commit();
    };
    load_kv(0);

    float b_row0 = rpb[3969 * TH + h];
    float b_col0 = SELF ? rpb[3970 * TH + h] : 0.f;
    float b_00   = SELF ? rpb[3971 * TH + h] : 0.f;

    for (int i = t; i < 63 * 63; i += 256) {
        int dq = i / 63, dr = i - dq * 63;
        tab[dq * 64 + dr] = rpb[i * TH + h];
    }

    const int wm = wid * 16;
    const int r0 = wm + (lane >> 2);
    float m[2] = {-1e30f, -1e30f};
    float l[2] = {0.f, 0.f};
    float oacc[8][4] = {};
    uint32_t qf[4][4];

    for (int kt = 0; kt < nkt; kt++) {
        if (kt + 1 < nkt) { load_kv(kt + 1); asm volatile("cp.async.wait_group 1;\n"); }
        else              { asm volatile("cp.async.wait_group 0;\n"); }
        __syncthreads();
        int buf = kt & 1;
        if (kt == 0) {
#pragma unroll
            for (int ks = 0; ks < 4; ks++)
                ldmA(qf[ks], Qb + ((wm + (lane & 15)) * 72 + ks * 16 + (lane >> 4) * 8) * 2);
        }
        float sacc[16][4];
#pragma unroll
        for (int nt = 0; nt < 16; nt++)
#pragma unroll
            for (int e = 0; e < 4; e++) sacc[nt][e] = 0.f;
#pragma unroll
        for (int ks = 0; ks < 4; ks++) {
#pragma unroll
            for (int ntp = 0; ntp < 8; ntp++) {
                uint32_t kf[4];
                ldmA(kf, Kb[buf] + ((ntp * 16 + (lane & 15)) * 72 + ks * 16 + (lane >> 4) * 8) * 2);
                uint32_t b0[2] = {kf[0], kf[2]};
                uint32_t b1[2] = {kf[1], kf[3]};
                mma_bf16(sacc[2 * ntp],     qf[ks], b0);
                mma_bf16(sacc[2 * ntp + 1], qf[ks], b1);
            }
        }
        float mloc[2] = {-1e30f, -1e30f};
#pragma unroll
        for (int nt = 0; nt < 16; nt++) {
#pragma unroll
            for (int e = 0; e < 4; e++) {
                int gk = kt * 128 + nt * 8 + (lane & 3) * 2 + (e & 1);
                int gq = q0 + r0 + (e >> 1) * 8;
                float s;
                bool ok = (gq < TN) && (gk < Nk) && (!SELF || gk <= gq);
                if (ok) {
                    float bias;
                    if (gq == 0) bias = (SELF && gk == 0) ? b_00 : b_row0;
                    else if (SELF && gk == 0) bias = b_col0;
                    else {
                        int qq = gq - 1, kk = SELF ? gk - 1 : gk;
                        int dq = ((qq >> 5) - (kk >> 5)) + 31;
                        int dr = ((qq & 31) - (kk & 31)) + 31;
                        bias = tab[dq * 64 + dr];
                    }
                    s = sacc[nt][e] * ATT_SCALE + bias;
                } else s = -1e30f;
                sacc[nt][e] = s;
                mloc[e >> 1] = fmaxf(mloc[e >> 1], s);
            }
        }
#pragma unroll
        for (int j = 0; j < 2; j++) {
#pragma unroll
            for (int o = 1; o < 4; o <<= 1)
                mloc[j] = fmaxf(mloc[j], __shfl_xor_sync(0xffffffffu, mloc[j], o));
            float mnew = fmaxf(m[j], mloc[j]);
            float alpha = __expf(m[j] - mnew);
            m[j] = mnew;
            l[j] *= alpha;
#pragma unroll
            for (int nt = 0; nt < 8; nt++) {
                oacc[nt][j * 2 + 0] *= alpha;
                oacc[nt][j * 2 + 1] *= alpha;
            }
        }
        float lsum[2] = {0.f, 0.f};
#pragma unroll
        for (int nt = 0; nt < 16; nt++) {
#pragma unroll
            for (int e = 0; e < 4; e++) {
                float p = __expf(sacc[nt][e] - m[e >> 1]);
                sacc[nt][e] = p;
                lsum[e >> 1] += p;
            }
        }
#pragma unroll
        for (int j = 0; j < 2; j++) {
#pragma unroll
            for (int o = 1; o < 4; o <<= 1)
                lsum[j] += __shfl_xor_sync(0xffffffffu, lsum[j], o);
            l[j] += lsum[j];
        }
#pragma unroll
        for (int kb = 0; kb < 8; kb++) {
            uint32_t pa[4];
            pa[0] = packbf(sacc[2 * kb][0],     sacc[2 * kb][1]);
            pa[1] = packbf(sacc[2 * kb][2],     sacc[2 * kb][3]);
            pa[2] = packbf(sacc[2 * kb + 1][0], sacc[2 * kb + 1][1]);
            pa[3] = packbf(sacc[2 * kb + 1][2], sacc[2 * kb + 1][3]);
#pragma unroll
            for (int ntp = 0; ntp < 4; ntp++) {
                uint32_t vf[4];
                ldmT4(vf, Vb[buf] + ((kb * 16 + (lane & 15)) * 72 + ntp * 16 + (lane >> 4) * 8) * 2);
                uint32_t vb0[2] = {vf[0], vf[1]};
                uint32_t vb1[2] = {vf[2], vf[3]};
                mma_bf16(oacc[2 * ntp],     pa, vb0);
                mma_bf16(oacc[2 * ntp + 1], pa, vb1);
            }
        }
        __syncthreads();
    }

    float inv[2] = {1.f / l[0], 1.f / l[1]};
#pragma unroll
    for (int nt = 0; nt < 8; nt++) {
        int dcol = nt * 8 + (lane & 3) * 2;
#pragma unroll
        for (int h2 = 0; h2 < 2; h2++) {
            int gq = q0 + r0 + h2 * 8;
            if (gq >= TN) continue;
            __nv_bfloat162 o;
            o.x = __float2bfloat16(oacc[nt][h2 * 2 + 0] * inv[h2]);
            o.y = __float2bfloat16(oacc[nt][h2 * 2 + 1] * inv[h2]);
            *(__nv_bfloat162*)(outp + ((size_t)b * TN + gq) * TE + h * TD + dcol) = o;
        }
    }
}

// ---------------- launch ----------------
extern "C" void kernel_launch(void* const* d_in, const int* in_sizes, int n_in,
                              void* d_out, int out_size) {
    (void)in_sizes; (void)n_in; (void)out_size;
    const float* x         = (const float*)d_in[0];
    const float* y         = (const float*)d_in[1];
    const float* n1g       = (const float*)d_in[2];
    const float* n1b       = (const float*)d_in[3];
    const float* n2g       = (const float*)d_in[4];
    const float* n2b       = (const float*)d_in[5];
    const float* n3g       = (const float*)d_in[6];
    const float* n3b       = (const float*)d_in[7];
    const float* sa_qkv_w  = (const float*)d_in[8];
    const float* sa_q_bias = (const float*)d_in[9];
    const float* sa_v_bias = (const float*)d_in[10];
    const float* sa_rpb    = (const float*)d_in[11];
    const float* sa_proj_w = (const float*)d_in[12];
    const float* sa_proj_b = (const float*)d_in[13];
    const float* ca_q_w    = (const float*)d_in[14];
    const float* ca_kv_w   = (const float*)d_in[15];
    const float* ca_q_bias = (const float*)d_in[16];
    const float* ca_v_bias = (const float*)d_in[17];
    const float* ca_rpb    = (const float*)d_in[18];
    const float* ca_proj_w = (const float*)d_in[19];
    const float* ca_proj_b = (const float*)d_in[20];
    const float* fc1_w     = (const float*)d_in[21];
    const float* fc1_b     = (const float*)d_in[22];
    const float* fc2_w     = (const float*)d_in[23];
    const float* fc2_b     = (const float*)d_in[24];
    const float* gamma1    = (const float*)d_in[25];
    const float* gamma2    = (const float*)d_in[26];
    const float* gamma3    = (const float*)d_in[27];
    float* out = (float*)d_out;

    float *p_b3, *p_b2;
    bf16 *p_hb, *p_yb, *p_qkvb, *p_kvb, *p_q2b, *p_attnb, *p_ffnb;
    bf16 *p_wqkv, *p_wkv, *p_wq, *p_wp1, *p_wp2, *p_wf1, *p_wf2;
    cudaGetSymbolAddress((void**)&p_hb, g_hb);
    cudaGetSymbolAddress((void**)&p_yb, g_yb);
    cudaGetSymbolAddress((void**)&p_qkvb, g_qkvb);
    cudaGetSymbolAddress((void**)&p_kvb, g_kvb);
    cudaGetSymbolAddress((void**)&p_q2b, g_q2b);
    cudaGetSymbolAddress((void**)&p_attnb, g_attnb);
    cudaGetSymbolAddress((void**)&p_ffnb, g_ffnb);
    cudaGetSymbolAddress((void**)&p_wqkv, g_wqkv);
    cudaGetSymbolAddress((void**)&p_wkv, g_wkv);
    cudaGetSymbolAddress((void**)&p_wq, g_wq);
    cudaGetSymbolAddress((void**)&p_wp1, g_wp1);
    cudaGetSymbolAddress((void**)&p_wp2, g_wp2);
    cudaGetSymbolAddress((void**)&p_wf1, g_wf1);
    cudaGetSymbolAddress((void**)&p_wf2, g_wf2);
    cudaGetSymbolAddress((void**)&p_b3, g_bias3);
    cudaGetSymbolAddress((void**)&p_b2, g_bias2);

    cudaFuncSetAttribute(flash_attn<true>,  cudaFuncAttributeMaxDynamicSharedMemorySize, SMEM_FLASH);
    cudaFuncSetAttribute(flash_attn<false>, cudaFuncAttributeMaxDynamicSharedMemorySize, SMEM_FLASH);
    cudaFuncSetAttribute(bgemm<0>, cudaFuncAttributeMaxDynamicSharedMemorySize, SMEM_GEMM);
    cudaFuncSetAttribute(bgemm<1>, cudaFuncAttributeMaxDynamicSharedMemorySize, SMEM_GEMM);
    cudaFuncSetAttribute(bgemm<2>, cudaFuncAttributeMaxDynamicSharedMemorySize, SMEM_GEMM);

    // all fp32->bf16 conversions in one launch (5242880 vec4 / 256)
    f2bf_all<<<20480, 256>>>(sa_qkv_w, ca_kv_w, ca_q_w, sa_proj_w, ca_proj_w,
                             fc1_w, fc2_w, y,
                             p_wqkv, p_wkv, p_wq, p_wp1, p_wp2, p_wf1, p_wf2, p_yb);
    build_bias_kernel<<<12, 256>>>(sa_q_bias, sa_v_bias, ca_v_bias);

    // ---- self attention ----
    ln_kernel<<<TM, 256>>>(x, n1g, n1b, p_hb);
    bgemm<0><<<dim3(24, 33), 256, SMEM_GEMM>>>(p_hb, TE, p_wqkv, TM, 3 * TE, TE,
                                               p_b3, nullptr, nullptr, nullptr, p_qkvb, 3 * TE);
    bgemm<0><<<dim3(16, 32), 256, SMEM_GEMM>>>(p_yb, TE, p_wkv, TB * TL, 2 * TE, TE,
                                               p_b2, nullptr, nullptr, nullptr, p_kvb, 2 * TE);
    flash_attn<true><<<dim3(9, 1, 64), 256, SMEM_FLASH>>>(p_qkvb, p_qkvb, sa_rpb, p_attnb);
    bgemm<2><<<dim3(8, 33), 256, SMEM_GEMM>>>(p_attnb, TE, p_wp1, TM, TE, TE,
                                              sa_proj_b, x, gamma1, out, nullptr, TE);

    // ---- cross attention ----
    ln_kernel<<<TM, 256>>>(out, n2g, n2b, p_hb);
    bgemm<0><<<dim3(8, 33), 256, SMEM_GEMM>>>(p_hb, TE, p_wq, TM, TE, TE,
                                              ca_q_bias, nullptr, nullptr, nullptr, p_q2b, TE);
    flash_attn<false><<<dim3(9, 1, 64), 256, SMEM_FLASH>>>(p_q2b, p_kvb, ca_rpb, p_attnb);
    bgemm<2><<<dim3(8, 33), 256, SMEM_GEMM>>>(p_attnb, TE, p_wp2, TM, TE, TE,
                                              ca_proj_b, out, gamma2, out, nullptr, TE);

    // ---- FFN ----
    ln_kernel<<<TM, 256>>>(out, n3g, n3b, p_hb);
    bgemm<1><<<dim3(32, 33), 256, SMEM_GEMM>>>(p_hb, TE, p_wf1, TM, TF, TE,
                                               fc1_b, nullptr, nullptr, nullptr, p_ffnb, TF);
    bgemm<2><<<dim3(8, 33), 256, SMEM_GEMM>>>(p_ffnb, TF, p_wf2, TM, TE, TF,
                                              fc2_b, out, gamma3, out, nullptr, TE);
}

// round 14
// speedup vs baseline: 1.0727x; 1.0727x over previous
#include <cuda_runtime.h>
#include <cuda_bf16.h>
#include <math.h>
#include <stdint.h>

typedef __nv_bfloat16 bf16;

// ---------------- problem constants ----------------
constexpr int TB = 4;
constexpr int TN = 1025;
constexpr int TL = 1024;
constexpr int TE = 1024;
constexpr int TH = 16;
constexpr int TD = 64;
constexpr int TF = 4096;
constexpr int TM = TB * TN;           // 4100
constexpr float ATT_SCALE = 0.125f;

// flash smem
constexpr int FTILE = 128 * 72;
constexpr int SMEM_FLASH = 5 * FTILE * 2 + 63 * 64 * 4;   // 108288 bytes

// gemm smem: 3 stages of (A 128x40 + B 128x40) bf16
constexpr int GSTAGE = (128 + 128) * 40;                  // halfwords per stage
constexpr int SMEM_GEMM = 3 * GSTAGE * 2;                 // 61440 bytes

// ---------------- scratch ----------------
__device__ bf16  g_hb  [(size_t)TM * TE];
__device__ bf16  g_yb  [(size_t)TB * TL * TE];
__device__ bf16  g_qkvb[(size_t)TM * 3 * TE];
__device__ bf16  g_kvb [(size_t)TB * TL * 2 * TE];
__device__ bf16  g_q2b [(size_t)TM * TE];
__device__ bf16  g_attnb[(size_t)TM * TE];
__device__ bf16  g_ffnb[(size_t)TM * TF];
__device__ bf16  g_wqkv[(size_t)3 * TE * TE];
__device__ bf16  g_wkv [(size_t)2 * TE * TE];
__device__ bf16  g_wq  [(size_t)TE * TE];
__device__ bf16  g_wp1 [(size_t)TE * TE];
__device__ bf16  g_wp2 [(size_t)TE * TE];
__device__ bf16  g_wf1 [(size_t)TF * TE];
__device__ bf16  g_wf2 [(size_t)TE * TF];
__device__ float g_bias3[3 * TE];
__device__ float g_bias2[2 * TE];

// ---------------- PTX helpers ----------------
__device__ __forceinline__ void cp16(uint32_t smem, const void* gmem, int bytes) {
    asm volatile("cp.async.cg.shared.global [%0], [%1], 16, %2;\n"
                 :: "r"(smem), "l"(gmem), "r"(bytes));
}
__device__ __forceinline__ void cp_commit() { asm volatile("cp.async.commit_group;\n"); }

__device__ __forceinline__ void ldmA(uint32_t* a, uint32_t addr) {
    asm volatile("ldmatrix.sync.aligned.m8n8.x4.shared.b16 {%0,%1,%2,%3}, [%4];\n"
                 : "=r"(a[0]), "=r"(a[1]), "=r"(a[2]), "=r"(a[3]) : "r"(addr));
}
__device__ __forceinline__ void ldmB(uint32_t* b, uint32_t addr) {
    asm volatile("ldmatrix.sync.aligned.m8n8.x2.shared.b16 {%0,%1}, [%2];\n"
                 : "=r"(b[0]), "=r"(b[1]) : "r"(addr));
}
__device__ __forceinline__ void ldmT4(uint32_t* b, uint32_t addr) {
    asm volatile("ldmatrix.sync.aligned.m8n8.x4.trans.shared.b16 {%0,%1,%2,%3}, [%4];\n"
                 : "=r"(b[0]), "=r"(b[1]), "=r"(b[2]), "=r"(b[3]) : "r"(addr));
}
__device__ __forceinline__ void mma_bf16(float* d, const uint32_t* a, const uint32_t* b) {
    asm volatile("mma.sync.aligned.m16n8k16.row.col.f32.bf16.bf16.f32 "
                 "{%0,%1,%2,%3}, {%4,%5,%6,%7}, {%8,%9}, {%0,%1,%2,%3};\n"
                 : "+f"(d[0]), "+f"(d[1]), "+f"(d[2]), "+f"(d[3])
                 : "r"(a[0]), "r"(a[1]), "r"(a[2]), "r"(a[3]), "r"(b[0]), "r"(b[1]));
}
__device__ __forceinline__ uint32_t packbf(float x, float y) {
    __nv_bfloat162 p = __floats2bfloat162_rn(x, y);
    return *(uint32_t*)&p;
}

// ---------------- reductions ----------------
__device__ __forceinline__ float block_sum(float v) {
    __shared__ float sm[32];
    int lane = threadIdx.x & 31, wid = threadIdx.x >> 5;
#pragma unroll
    for (int o = 16; o > 0; o >>= 1) v += __shfl_xor_sync(0xffffffffu, v, o);
    if (lane == 0) sm[wid] = v;
    __syncthreads();
    if (wid == 0) {
        v = (lane < (int)(blockDim.x >> 5)) ? sm[lane] : 0.f;
#pragma unroll
        for (int o = 16; o > 0; o >>= 1) v += __shfl_xor_sync(0xffffffffu, v, o);
        if (lane == 0) sm[0] = v;
    }
    __syncthreads();
    float r = sm[0];
    __syncthreads();
    return r;
}

// ---------------- fused fp32->bf16 conversion for all weights + y (one launch) ----------------
__global__ void f2bf_all(const float* __restrict__ s0, const float* __restrict__ s1,
                         const float* __restrict__ s2, const float* __restrict__ s3,
                         const float* __restrict__ s4, const float* __restrict__ s5,
                         const float* __restrict__ s6, const float* __restrict__ s7,
                         bf16* d0, bf16* d1, bf16* d2, bf16* d3,
                         bf16* d4, bf16* d5, bf16* d6, bf16* d7) {
    long i = (long)blockIdx.x * 256 + threadIdx.x;   // vec4 index
    const float* s; bf16* d;
    if (i < 786432)                    { s = s0; d = d0; }
    else if ((i -= 786432) < 524288)   { s = s1; d = d1; }
    else if ((i -= 524288) < 262144)   { s = s2; d = d2; }
    else if ((i -= 262144) < 262144)   { s = s3; d = d3; }
    else if ((i -= 262144) < 262144)   { s = s4; d = d4; }
    else if ((i -= 262144) < 1048576)  { s = s5; d = d5; }
    else if ((i -= 1048576) < 1048576) { s = s6; d = d6; }
    else { i -= 1048576;                 s = s7; d = d7; }
    float4 v = ((const float4*)s)[i];
    __nv_bfloat162 p0, p1;
    p0.x = __float2bfloat16(v.x); p0.y = __float2bfloat16(v.y);
    p1.x = __float2bfloat16(v.z); p1.y = __float2bfloat16(v.w);
    __nv_bfloat162* o = (__nv_bfloat162*)(d + i * 4);
    o[0] = p0; o[1] = p1;
}

__global__ void build_bias_kernel(const float* __restrict__ saq,
                                  const float* __restrict__ sav,
                                  const float* __restrict__ cav) {
    int i = blockIdx.x * 256 + threadIdx.x;
    if (i < 3 * TE)
        g_bias3[i] = (i < TE) ? saq[i] : ((i < 2 * TE) ? 0.f : sav[i - 2 * TE]);
    if (i < 2 * TE)
        g_bias2[i] = (i < TE) ? 0.f : cav[i - TE];
}

// LayerNorm: fp32 in -> bf16 out
__global__ void ln_kernel(const float* __restrict__ x, const float* __restrict__ g,
                          const float* __restrict__ b, bf16* __restrict__ out) {
    int row = blockIdx.x;
    int t = threadIdx.x;
    float4 v = ((const float4*)(x + (size_t)row * TE))[t];
    float mean = block_sum(v.x + v.y + v.z + v.w) * (1.f / TE);
    float dx = v.x - mean, dy = v.y - mean, dz = v.z - mean, dw = v.w - mean;
    float var = block_sum(dx * dx + dy * dy + dz * dz + dw * dw) * (1.f / TE);
    float rstd = rsqrtf(var + 1e-5f);
    float4 gg = ((const float4*)g)[t];
    float4 bb = ((const float4*)b)[t];
    __nv_bfloat162 p0, p1;
    p0.x = __float2bfloat16(dx * rstd * gg.x + bb.x);
    p0.y = __float2bfloat16(dy * rstd * gg.y + bb.y);
    p1.x = __float2bfloat16(dz * rstd * gg.z + bb.z);
    p1.y = __float2bfloat16(dw * rstd * gg.w + bb.w);
    __nv_bfloat162* o = (__nv_bfloat162*)(out + (size_t)row * TE);
    o[2 * t] = p0; o[2 * t + 1] = p1;
}

// ---------------- bf16 tensor-core GEMM (R11-exact: 128x128 tile, 3-stage, x2 B-frags) ----------------
// C(M,Ncols) = epi(A(M,K) @ W(Ncols,K)^T + bias)
// EPI 0: bias -> bf16 Cb;  EPI 1: gelu(bias) -> bf16 Cb;  EPI 2: res + gamma*(acc+bias) -> float Cf
template<int EPI>
__global__ void __launch_bounds__(256)
bgemm(const bf16* __restrict__ A, int lda,
      const bf16* __restrict__ W,
      int M, int Ncols, int K,
      const float* __restrict__ bias,
      const float* __restrict__ res,
      const float* __restrict__ gamma,
      float* __restrict__ Cf, bf16* __restrict__ Cb, int ldc) {
    extern __shared__ bf16 smg[];
    const int t = threadIdx.x, lane = t & 31, wid = t >> 5;
    const int m0 = blockIdx.y * 128, n0 = blockIdx.x * 128;
    uint32_t sAb[3], sBb[3];
#pragma unroll
    for (int s = 0; s < 3; s++) {
        sAb[s] = (uint32_t)__cvta_generic_to_shared(smg + s * GSTAGE);
        sBb[s] = sAb[s] + 128 * 40 * 2;
    }

    auto load_stage = [&](int s) {
        int k0 = s * 32, buf = s % 3;
#pragma unroll
        for (int i = 0; i < 2; i++) {
            int c = t + i * 256; int row = c >> 2; int cc = c & 3;
            bool v = (m0 + row) < M;
            const bf16* src = A + (size_t)(v ? m0 + row : 0) * lda + k0 + cc * 8;
            cp16(sAb[buf] + (row * 40 + cc * 8) * 2, src, v ? 16 : 0);
        }
#pragma unroll
        for (int i = 0; i < 2; i++) {
            int c = t + i * 256; int row = c >> 2; int cc = c & 3;
            bool v = (n0 + row) < Ncols;
            const bf16* src = W + (size_t)(v ? n0 + row : 0) * K + k0 + cc * 8;
            cp16(sBb[buf] + (row * 40 + cc * 8) * 2, src, v ? 16 : 0);
        }
        cp_commit();
    };

    const int wm = (wid >> 2) * 64, wn = (wid & 3) * 32;
    float acc[4][4][4] = {};
    const int NS = K / 32;
    load_stage(0);
    if (NS > 1) load_stage(1);
    for (int s = 0; s < NS; s++) {
        if (s + 1 < NS) asm volatile("cp.async.wait_group 1;\n");
        else            asm volatile("cp.async.wait_group 0;\n");
        __syncthreads();
        int buf = s % 3;
#pragma unroll
        for (int ks = 0; ks < 2; ks++) {
            uint32_t af[4][4];
#pragma unroll
            for (int mt = 0; mt < 4; mt++)
                ldmA(af[mt], sAb[buf] + ((wm + mt * 16 + (lane & 15)) * 40 + ks * 16 + (lane >> 4) * 8) * 2);
            uint32_t bfr[4][2];
#pragma unroll
            for (int nt = 0; nt < 4; nt++)
                ldmB(bfr[nt], sBb[buf] + ((wn + nt * 8 + (lane & 7)) * 40 + ks * 16 + ((lane >> 3) & 1) * 8) * 2);
#pragma unroll
            for (int mt = 0; mt < 4; mt++)
#pragma unroll
                for (int nt = 0; nt < 4; nt++) mma_bf16(acc[mt][nt], af[mt], bfr[nt]);
        }
        if (s + 2 < NS) load_stage(s + 2);
    }

#pragma unroll
    for (int mt = 0; mt < 4; mt++)
#pragma unroll
        for (int nt = 0; nt < 4; nt++) {
            int col = n0 + wn + nt * 8 + (lane & 3) * 2;
            float b0 = bias[col], b1 = bias[col + 1];
#pragma unroll
            for (int h2 = 0; h2 < 2; h2++) {
                int gm = m0 + wm + mt * 16 + (lane >> 2) + h2 * 8;
                if (gm >= M) continue;
                float v0 = acc[mt][nt][h2 * 2 + 0] + b0;
                float v1 = acc[mt][nt][h2 * 2 + 1] + b1;
                if (EPI == 1) {
                    v0 = 0.5f * v0 * (1.f + erff(v0 * 0.70710678118654752f));
                    v1 = 0.5f * v1 * (1.f + erff(v1 * 0.70710678118654752f));
                }
                if (EPI == 2) {
                    float2 r = *(const float2*)(res + (size_t)gm * ldc + col);
                    v0 = r.x + gamma[col] * v0;
                    v1 = r.y + gamma[col + 1] * v1;
                    *(float2*)(Cf + (size_t)gm * ldc + col) = make_float2(v0, v1);
                } else {
                    __nv_bfloat162 o;
                    o.x = __float2bfloat16(v0); o.y = __float2bfloat16(v1);
                    *(__nv_bfloat162*)(Cb + (size_t)gm * ldc + col) = o;
                }
            }
        }
}

// ---------------- fused flash attention (R11-exact) ----------------
template<bool SELF>
__global__ void __launch_bounds__(256)
flash_attn(const bf16* __restrict__ qsrc, const bf16* __restrict__ kvsrc,
           const float* __restrict__ rpb, bf16* __restrict__ outp) {
    extern __shared__ char dsm[];
    bf16* Qs = (bf16*)dsm;
    bf16* Ks = Qs + FTILE;
    bf16* Vs = Ks + 2 * FTILE;
    float* tab = (float*)(dsm + 5 * FTILE * 2);

    const int t = threadIdx.x, lane = t & 31, wid = t >> 5;
    const int b = blockIdx.z >> 4, h = blockIdx.z & 15;
    const int q0 = blockIdx.x * 128;
    const int Nk = SELF ? TN : TL;
    const int nkt = SELF ? ((int)blockIdx.x + 1) : 8;
    const int ldq = SELF ? 3 * TE : TE;
    const int ldk = SELF ? 3 * TE : 2 * TE;
    const bf16* qp = SELF ? qsrc + (size_t)b * TN * 3 * TE + h * TD
                          : qsrc + (size_t)b * TN * TE + h * TD;
    const bf16* kp = SELF ? kvsrc + (size_t)b * TN * 3 * TE + TE + h * TD
                          : kvsrc + (size_t)b * TL * 2 * TE + h * TD;
    const bf16* vp = SELF ? kvsrc + (size_t)b * TN * 3 * TE + 2 * TE + h * TD
                          : kvsrc + (size_t)b * TL * 2 * TE + TE + h * TD;

    uint32_t Qb = (uint32_t)__cvta_generic_to_shared(Qs);
    uint32_t Kb[2] = {(uint32_t)__cvta_generic_to_shared(Ks),
                      (uint32_t)__cvta_generic_to_shared(Ks + FTILE)};
    uint32_t Vb[2] = {(uint32_t)__cvta_generic_to_shared(Vs),
                      (uint32_t)__cvta_generic_to_shared(Vs + FTILE)};

#pragma unroll
    for (int i = 0; i < 4; i++) {
        int c = t + i * 256; int row = c >> 3; int cc = c & 7;
        bool v = (q0 + row) < TN;
        cp16(Qb + (row * 72 + cc * 8) * 2, qp + (size_t)(v ? q0 + row : 0) * ldq + cc * 8, v ? 16 : 0);
    }
    auto load_kv = [&](int kt) {
        int buf = kt & 1;
#pragma unroll
        for (int i = 0; i < 4; i++) {
            int c = t + i * 256; int row = c >> 3; int cc = c & 7;
            int gk = kt * 128 + row;
            bool v = gk < Nk;
            const bf16* ksrc2 = kp + (size_t)(v ? gk : 0) * ldk + cc * 8;
            const bf16* vsrc2 = vp + (size_t)(v ? gk : 0) * ldk + cc * 8;
            cp16(Kb[buf] + (row * 72 + cc * 8) * 2, ksrc2, v ? 16 : 0);
            cp16(Vb[buf] + (row * 72 + cc * 8) * 2, vsrc2, v ? 16 : 0);
        }
        cp_commit();
    };
    load_kv(0);

    float b_row0 = rpb[3969 * TH + h];
    float b_col0 = SELF ? rpb[3970 * TH + h] : 0.f;
    float b_00   = SELF ? rpb[3971 * TH + h] : 0.f;

    for (int i = t; i < 63 * 63; i += 256) {
        int dq = i / 63, dr = i - dq * 63;
        tab[dq * 64 + dr] = rpb[i * TH + h];
    }

    const int wm = wid * 16;
    const int r0 = wm + (lane >> 2);
    float m[2] = {-1e30f, -1e30f};
    float l[2] = {0.f, 0.f};
    float oacc[8][4] = {};
    uint32_t qf[4][4];

    for (int kt = 0; kt < nkt; kt++) {
        if (kt + 1 < nkt) { load_kv(kt + 1); asm volatile("cp.async.wait_group 1;\n"); }
        else              { asm volatile("cp.async.wait_group 0;\n"); }
        __syncthreads();
        int buf = kt & 1;
        if (kt == 0) {
#pragma unroll
            for (int ks = 0; ks < 4; ks++)
                ldmA(qf[ks], Qb + ((wm + (lane & 15)) * 72 + ks * 16 + (lane >> 4) * 8) * 2);
        }
        float sacc[16][4];
#pragma unroll
        for (int nt = 0; nt < 16; nt++)
#pragma unroll
            for (int e = 0; e < 4; e++) sacc[nt][e] = 0.f;
#pragma unroll
        for (int ks = 0; ks < 4; ks++) {
#pragma unroll
            for (int ntp = 0; ntp < 8; ntp++) {
                uint32_t kf[4];
                ldmA(kf, Kb[buf] + ((ntp * 16 + (lane & 15)) * 72 + ks * 16 + (lane >> 4) * 8) * 2);
                uint32_t b0[2] = {kf[0], kf[2]};
                uint32_t b1[2] = {kf[1], kf[3]};
                mma_bf16(sacc[2 * ntp],     qf[ks], b0);
                mma_bf16(sacc[2 * ntp + 1], qf[ks], b1);
            }
        }
        float mloc[2] = {-1e30f, -1e30f};
#pragma unroll
        for (int nt = 0; nt < 16; nt++) {
#pragma unroll
            for (int e = 0; e < 4; e++) {
                int gk = kt * 128 + nt * 8 + (lane & 3) * 2 + (e & 1);
                int gq = q0 + r0 + (e >> 1) * 8;
                float s;
                bool ok = (gq < TN) && (gk < Nk) && (!SELF || gk <= gq);
                if (ok) {
                    float bias;
                    if (gq == 0) bias = (SELF && gk == 0) ? b_00 : b_row0;
                    else if (SELF && gk == 0) bias = b_col0;
                    else {
                        int qq = gq - 1, kk = SELF ? gk - 1 : gk;
                        int dq = ((qq >> 5) - (kk >> 5)) + 31;
                        int dr = ((qq & 31) - (kk & 31)) + 31;
                        bias = tab[dq * 64 + dr];
                    }
                    s = sacc[nt][e] * ATT_SCALE + bias;
                } else s = -1e30f;
                sacc[nt][e] = s;
                mloc[e >> 1] = fmaxf(mloc[e >> 1], s);
            }
        }
#pragma unroll
        for (int j = 0; j < 2; j++) {
#pragma unroll
            for (int o = 1; o < 4; o <<= 1)
                mloc[j] = fmaxf(mloc[j], __shfl_xor_sync(0xffffffffu, mloc[j], o));
            float mnew = fmaxf(m[j], mloc[j]);
            float alpha = __expf(m[j] - mnew);
            m[j] = mnew;
            l[j] *= alpha;
#pragma unroll
            for (int nt = 0; nt < 8; nt++) {
                oacc[nt][j * 2 + 0] *= alpha;
                oacc[nt][j * 2 + 1] *= alpha;
            }
        }
        float lsum[2] = {0.f, 0.f};
#pragma unroll
        for (int nt = 0; nt < 16; nt++) {
#pragma unroll
            for (int e = 0; e < 4; e++) {
                float p = __expf(sacc[nt][e] - m[e >> 1]);
                sacc[nt][e] = p;
                lsum[e >> 1] += p;
            }
        }
#pragma unroll
        for (int j = 0; j < 2; j++) {
#pragma unroll
            for (int o = 1; o < 4; o <<= 1)
                lsum[j] += __shfl_xor_sync(0xffffffffu, lsum[j], o);
            l[j] += lsum[j];
        }
#pragma unroll
        for (int kb = 0; kb < 8; kb++) {
            uint32_t pa[4];
            pa[0] = packbf(sacc[2 * kb][0],     sacc[2 * kb][1]);
            pa[1] = packbf(sacc[2 * kb][2],     sacc[2 * kb][3]);
            pa[2] = packbf(sacc[2 * kb + 1][0], sacc[2 * kb + 1][1]);
            pa[3] = packbf(sacc[2 * kb + 1][2], sacc[2 * kb + 1][3]);
#pragma unroll
            for (int ntp = 0; ntp < 4; ntp++) {
                uint32_t vf[4];
                ldmT4(vf, Vb[buf] + ((kb * 16 + (lane & 15)) * 72 + ntp * 16 + (lane >> 4) * 8) * 2);
                uint32_t vb0[2] = {vf[0], vf[1]};
                uint32_t vb1[2] = {vf[2], vf[3]};
                mma_bf16(oacc[2 * ntp],     pa, vb0);
                mma_bf16(oacc[2 * ntp + 1], pa, vb1);
            }
        }
        __syncthreads();
    }

    float inv[2] = {1.f / l[0], 1.f / l[1]};
#pragma unroll
    for (int nt = 0; nt < 8; nt++) {
        int dcol = nt * 8 + (lane & 3) * 2;
#pragma unroll
        for (int h2 = 0; h2 < 2; h2++) {
            int gq = q0 + r0 + h2 * 8;
            if (gq >= TN) continue;
            __nv_bfloat162 o;
            o.x = __float2bfloat16(oacc[nt][h2 * 2 + 0] * inv[h2]);
            o.y = __float2bfloat16(oacc[nt][h2 * 2 + 1] * inv[h2]);
            *(__nv_bfloat162*)(outp + ((size_t)b * TN + gq) * TE + h * TD + dcol) = o;
        }
    }
}

// ---------------- launch ----------------
extern "C" void kernel_launch(void* const* d_in, const int* in_sizes, int n_in,
                              void* d_out, int out_size) {
    (void)in_sizes; (void)n_in; (void)out_size;
    const float* x         = (const float*)d_in[0];
    const float* y         = (const float*)d_in[1];
    const float* n1g       = (const float*)d_in[2];
    const float* n1b       = (const float*)d_in[3];
    const float* n2g       = (const float*)d_in[4];
    const float* n2b       = (const float*)d_in[5];
    const float* n3g       = (const float*)d_in[6];
    const float* n3b       = (const float*)d_in[7];
    const float* sa_qkv_w  = (const float*)d_in[8];
    const float* sa_q_bias = (const float*)d_in[9];
    const float* sa_v_bias = (const float*)d_in[10];
    const float* sa_rpb    = (const float*)d_in[11];
    const float* sa_proj_w = (const float*)d_in[12];
    const float* sa_proj_b = (const float*)d_in[13];
    const float* ca_q_w    = (const float*)d_in[14];
    const float* ca_kv_w   = (const float*)d_in[15];
    const float* ca_q_bias = (const float*)d_in[16];
    const float* ca_v_bias = (const float*)d_in[17];
    const float* ca_rpb    = (const float*)d_in[18];
    const float* ca_proj_w = (const float*)d_in[19];
    const float* ca_proj_b = (const float*)d_in[20];
    const float* fc1_w     = (const float*)d_in[21];
    const float* fc1_b     = (const float*)d_in[22];
    const float* fc2_w     = (const float*)d_in[23];
    const float* fc2_b     = (const float*)d_in[24];
    const float* gamma1    = (const float*)d_in[25];
    const float* gamma2    = (const float*)d_in[26];
    const float* gamma3    = (const float*)d_in[27];
    float* out = (float*)d_out;

    float *p_b3, *p_b2;
    bf16 *p_hb, *p_yb, *p_qkvb, *p_kvb, *p_q2b, *p_attnb, *p_ffnb;
    bf16 *p_wqkv, *p_wkv, *p_wq, *p_wp1, *p_wp2, *p_wf1, *p_wf2;
    cudaGetSymbolAddress((void**)&p_hb, g_hb);
    cudaGetSymbolAddress((void**)&p_yb, g_yb);
    cudaGetSymbolAddress((void**)&p_qkvb, g_qkvb);
    cudaGetSymbolAddress((void**)&p_kvb, g_kvb);
    cudaGetSymbolAddress((void**)&p_q2b, g_q2b);
    cudaGetSymbolAddress((void**)&p_attnb, g_attnb);
    cudaGetSymbolAddress((void**)&p_ffnb, g_ffnb);
    cudaGetSymbolAddress((void**)&p_wqkv, g_wqkv);
    cudaGetSymbolAddress((void**)&p_wkv, g_wkv);
    cudaGetSymbolAddress((void**)&p_wq, g_wq);
    cudaGetSymbolAddress((void**)&p_wp1, g_wp1);
    cudaGetSymbolAddress((void**)&p_wp2, g_wp2);
    cudaGetSymbolAddress((void**)&p_wf1, g_wf1);
    cudaGetSymbolAddress((void**)&p_wf2, g_wf2);
    cudaGetSymbolAddress((void**)&p_b3, g_bias3);
    cudaGetSymbolAddress((void**)&p_b2, g_bias2);

    cudaFuncSetAttribute(flash_attn<true>,  cudaFuncAttributeMaxDynamicSharedMemorySize, SMEM_FLASH);
    cudaFuncSetAttribute(flash_attn<false>, cudaFuncAttributeMaxDynamicSharedMemorySize, SMEM_FLASH);
    cudaFuncSetAttribute(bgemm<0>, cudaFuncAttributeMaxDynamicSharedMemorySize, SMEM_GEMM);
    cudaFuncSetAttribute(bgemm<1>, cudaFuncAttributeMaxDynamicSharedMemorySize, SMEM_GEMM);
    cudaFuncSetAttribute(bgemm<2>, cudaFuncAttributeMaxDynamicSharedMemorySize, SMEM_GEMM);

    // all fp32->bf16 conversions in one launch (5242880 vec4 / 256)
    f2bf_all<<<20480, 256>>>(sa_qkv_w, ca_kv_w, ca_q_w, sa_proj_w, ca_proj_w,
                             fc1_w, fc2_w, y,
                             p_wqkv, p_wkv, p_wq, p_wp1, p_wp2, p_wf1, p_wf2, p_yb);
    build_bias_kernel<<<12, 256>>>(sa_q_bias, sa_v_bias, ca_v_bias);

    // ---- self attention ----
    ln_kernel<<<TM, 256>>>(x, n1g, n1b, p_hb);
    bgemm<0><<<dim3(24, 33), 256, SMEM_GEMM>>>(p_hb, TE, p_wqkv, TM, 3 * TE, TE,
                                               p_b3, nullptr, nullptr, nullptr, p_qkvb, 3 * TE);
    bgemm<0><<<dim3(16, 32), 256, SMEM_GEMM>>>(p_yb, TE, p_wkv, TB * TL, 2 * TE, TE,
                                               p_b2, nullptr, nullptr, nullptr, p_kvb, 2 * TE);
    flash_attn<true><<<dim3(9, 1, 64), 256, SMEM_FLASH>>>(p_qkvb, p_qkvb, sa_rpb, p_attnb);
    bgemm<2><<<dim3(8, 33), 256, SMEM_GEMM>>>(p_attnb, TE, p_wp1, TM, TE, TE,
                                              sa_proj_b, x, gamma1, out, nullptr, TE);

    // ---- cross attention ----
    ln_kernel<<<TM, 256>>>(out, n2g, n2b, p_hb);
    bgemm<0><<<dim3(8, 33), 256, SMEM_GEMM>>>(p_hb, TE, p_wq, TM, TE, TE,
                                              ca_q_bias, nullptr, nullptr, nullptr, p_q2b, TE);
    flash_attn<false><<<dim3(9, 1, 64), 256, SMEM_FLASH>>>(p_q2b, p_kvb, ca_rpb, p_attnb);
    bgemm<2><<<dim3(8, 33), 256, SMEM_GEMM>>>(p_attnb, TE, p_wp2, TM, TE, TE,
                                              ca_proj_b, out, gamma2, out, nullptr, TE);

    // ---- FFN ----
    ln_kernel<<<TM, 256>>>(out, n3g, n3b, p_hb);
    bgemm<1><<<dim3(32, 33), 256, SMEM_GEMM>>>(p_hb, TE, p_wf1, TM, TF, TE,
                                               fc1_b, nullptr, nullptr, nullptr, p_ffnb, TF);
    bgemm<2><<<dim3(8, 33), 256, SMEM_GEMM>>>(p_ffnb, TF, p_wf2, TM, TE, TF,
                                              fc2_b, out, gamma3, out, nullptr, TE);
}

// round 15
// speedup vs baseline: 1.2034x; 1.1218x over previous
#include <cuda_runtime.h>
#include <cuda_bf16.h>
#include <math.h>
#include <stdint.h>

typedef __nv_bfloat16 bf16;

// ---------------- problem constants ----------------
constexpr int TB = 4;
constexpr int TN = 1025;
constexpr int TL = 1024;
constexpr int TE = 1024;
constexpr int TH = 16;
constexpr int TD = 64;
constexpr int TF = 4096;
constexpr int TM = TB * TN;           // 4100
constexpr float ATT_SCALE = 0.125f;

// flash smem
constexpr int FTILE = 128 * 72;
constexpr int SMEM_FLASH = 5 * FTILE * 2 + 63 * 64 * 4;   // 108288 bytes

// gemm smem: 3 stages of (A 128x40 + B 128x40) bf16
constexpr int GSTAGE = (128 + 128) * 40;                  // halfwords per stage
constexpr int SMEM_GEMM = 3 * GSTAGE * 2;                 // 61440 bytes

// ---------------- scratch ----------------
__device__ bf16  g_hb  [(size_t)TM * TE];
__device__ bf16  g_yb  [(size_t)TB * TL * TE];
__device__ bf16  g_qkvb[(size_t)TM * 3 * TE];
__device__ bf16  g_kvb [(size_t)TB * TL * 2 * TE];
__device__ bf16  g_q2b [(size_t)TM * TE];
__device__ bf16  g_attnb[(size_t)TM * TE];
__device__ bf16  g_ffnb[(size_t)TM * TF];
__device__ bf16  g_wqkv[(size_t)3 * TE * TE];
__device__ bf16  g_wkv [(size_t)2 * TE * TE];
__device__ bf16  g_wq  [(size_t)TE * TE];
__device__ bf16  g_wp1 [(size_t)TE * TE];
__device__ bf16  g_wp2 [(size_t)TE * TE];
__device__ bf16  g_wf1 [(size_t)TF * TE];
__device__ bf16  g_wf2 [(size_t)TE * TF];
__device__ float g_bias3[3 * TE];
__device__ float g_bias2[2 * TE];

// ---------------- PTX helpers ----------------
__device__ __forceinline__ void cp16(uint32_t smem, const void* gmem, int bytes) {
    asm volatile("cp.async.cg.shared.global [%0], [%1], 16, %2;\n"
                 :: "r"(smem), "l"(gmem), "r"(bytes));
}
__device__ __forceinline__ void cp_commit() { asm volatile("cp.async.commit_group;\n"); }

__device__ __forceinline__ void ldmA(uint32_t* a, uint32_t addr) {
    asm volatile("ldmatrix.sync.aligned.m8n8.x4.shared.b16 {%0,%1,%2,%3}, [%4];\n"
                 : "=r"(a[0]), "=r"(a[1]), "=r"(a[2]), "=r"(a[3]) : "r"(addr));
}
__device__ __forceinline__ void ldmB(uint32_t* b, uint32_t addr) {
    asm volatile("ldmatrix.sync.aligned.m8n8.x2.shared.b16 {%0,%1}, [%2];\n"
                 : "=r"(b[0]), "=r"(b[1]) : "r"(addr));
}
__device__ __forceinline__ void ldmT4(uint32_t* b, uint32_t addr) {
    asm volatile("ldmatrix.sync.aligned.m8n8.x4.trans.shared.b16 {%0,%1,%2,%3}, [%4];\n"
                 : "=r"(b[0]), "=r"(b[1]), "=r"(b[2]), "=r"(b[3]) : "r"(addr));
}
__device__ __forceinline__ void mma_bf16(float* d, const uint32_t* a, const uint32_t* b) {
    asm volatile("mma.sync.aligned.m16n8k16.row.col.f32.bf16.bf16.f32 "
                 "{%0,%1,%2,%3}, {%4,%5,%6,%7}, {%8,%9}, {%0,%1,%2,%3};\n"
                 : "+f"(d[0]), "+f"(d[1]), "+f"(d[2]), "+f"(d[3])
                 : "r"(a[0]), "r"(a[1]), "r"(a[2]), "r"(a[3]), "r"(b[0]), "r"(b[1]));
}
__device__ __forceinline__ uint32_t packbf(float x, float y) {
    __nv_bfloat162 p = __floats2bfloat162_rn(x, y);
    return *(uint32_t*)&p;
}

// ---------------- reductions ----------------
__device__ __forceinline__ float block_sum(float v) {
    __shared__ float sm[32];
    int lane = threadIdx.x & 31, wid = threadIdx.x >> 5;
#pragma unroll
    for (int o = 16; o > 0; o >>= 1) v += __shfl_xor_sync(0xffffffffu, v, o);
    if (lane == 0) sm[wid] = v;
    __syncthreads();
    if (wid == 0) {
        v = (lane < (int)(blockDim.x >> 5)) ? sm[lane] : 0.f;
#pragma unroll
        for (int o = 16; o > 0; o >>= 1) v += __shfl_xor_sync(0xffffffffu, v, o);
        if (lane == 0) sm[0] = v;
    }
    __syncthreads();
    float r = sm[0];
    __syncthreads();
    return r;
}

// ---------------- fused fp32->bf16 conversion (one launch) ----------------
__global__ void f2bf_all(const float* __restrict__ s0, const float* __restrict__ s1,
                         const float* __restrict__ s2, const float* __restrict__ s3,
                         const float* __restrict__ s4, const float* __restrict__ s5,
                         const float* __restrict__ s6, const float* __restrict__ s7,
                         bf16* d0, bf16* d1, bf16* d2, bf16* d3,
                         bf16* d4, bf16* d5, bf16* d6, bf16* d7) {
    long i = (long)blockIdx.x * 256 + threadIdx.x;   // vec4 index
    const float* s; bf16* d;
    if (i < 786432)                    { s = s0; d = d0; }
    else if ((i -= 786432) < 524288)   { s = s1; d = d1; }
    else if ((i -= 524288) < 262144)   { s = s2; d = d2; }
    else if ((i -= 262144) < 262144)   { s = s3; d = d3; }
    else if ((i -= 262144) < 262144)   { s = s4; d = d4; }
    else if ((i -= 262144) < 1048576)  { s = s5; d = d5; }
    else if ((i -= 1048576) < 1048576) { s = s6; d = d6; }
    else { i -= 1048576;                 s = s7; d = d7; }
    float4 v = ((const float4*)s)[i];
    __nv_bfloat162 p0, p1;
    p0.x = __float2bfloat16(v.x); p0.y = __float2bfloat16(v.y);
    p1.x = __float2bfloat16(v.z); p1.y = __float2bfloat16(v.w);
    __nv_bfloat162* o = (__nv_bfloat162*)(d + i * 4);
    o[0] = p0; o[1] = p1;
}

__global__ void build_bias_kernel(const float* __restrict__ saq,
                                  const float* __restrict__ sav,
                                  const float* __restrict__ cav) {
    int i = blockIdx.x * 256 + threadIdx.x;
    if (i < 3 * TE)
        g_bias3[i] = (i < TE) ? saq[i] : ((i < 2 * TE) ? 0.f : sav[i - 2 * TE]);
    if (i < 2 * TE)
        g_bias2[i] = (i < TE) ? 0.f : cav[i - TE];
}

// LayerNorm: fp32 in -> bf16 out
__global__ void ln_kernel(const float* __restrict__ x, const float* __restrict__ g,
                          const float* __restrict__ b, bf16* __restrict__ out) {
    int row = blockIdx.x;
    int t = threadIdx.x;
    float4 v = ((const float4*)(x + (size_t)row * TE))[t];
    float mean = block_sum(v.x + v.y + v.z + v.w) * (1.f / TE);
    float dx = v.x - mean, dy = v.y - mean, dz = v.z - mean, dw = v.w - mean;
    float var = block_sum(dx * dx + dy * dy + dz * dz + dw * dw) * (1.f / TE);
    float rstd = rsqrtf(var + 1e-5f);
    float4 gg = ((const float4*)g)[t];
    float4 bb = ((const float4*)b)[t];
    __nv_bfloat162 p0, p1;
    p0.x = __float2bfloat16(dx * rstd * gg.x + bb.x);
    p0.y = __float2bfloat16(dy * rstd * gg.y + bb.y);
    p1.x = __float2bfloat16(dz * rstd * gg.z + bb.z);
    p1.y = __float2bfloat16(dw * rstd * gg.w + bb.w);
    __nv_bfloat162* o = (__nv_bfloat162*)(out + (size_t)row * TE);
    o[2 * t] = p0; o[2 * t + 1] = p1;
}

// ---------------- bf16 tensor-core GEMM (R11-exact) ----------------
template<int EPI>
__global__ void __launch_bounds__(256)
bgemm(const bf16* __restrict__ A, int lda,
      const bf16* __restrict__ W,
      int M, int Ncols, int K,
      const float* __restrict__ bias,
      const float* __restrict__ res,
      const float* __restrict__ gamma,
      float* __restrict__ Cf, bf16* __restrict__ Cb, int ldc) {
    extern __shared__ bf16 smg[];
    const int t = threadIdx.x, lane = t & 31, wid = t >> 5;
    const int m0 = blockIdx.y * 128, n0 = blockIdx.x * 128;
    uint32_t sAb[3], sBb[3];
#pragma unroll
    for (int s = 0; s < 3; s++) {
        sAb[s] = (uint32_t)__cvta_generic_to_shared(smg + s * GSTAGE);
        sBb[s] = sAb[s] + 128 * 40 * 2;
    }

    auto load_stage = [&](int s) {
        int k0 = s * 32, buf = s % 3;
#pragma unroll
        for (int i = 0; i < 2; i++) {
            int c = t + i * 256; int row = c >> 2; int cc = c & 3;
            bool v = (m0 + row) < M;
            const bf16* src = A + (size_t)(v ? m0 + row : 0) * lda + k0 + cc * 8;
            cp16(sAb[buf] + (row * 40 + cc * 8) * 2, src, v ? 16 : 0);
        }
#pragma unroll
        for (int i = 0; i < 2; i++) {
            int c = t + i * 256; int row = c >> 2; int cc = c & 3;
            bool v = (n0 + row) < Ncols;
            const bf16* src = W + (size_t)(v ? n0 + row : 0) * K + k0 + cc * 8;
            cp16(sBb[buf] + (row * 40 + cc * 8) * 2, src, v ? 16 : 0);
        }
        cp_commit();
    };

    const int wm = (wid >> 2) * 64, wn = (wid & 3) * 32;
    float acc[4][4][4] = {};
    const int NS = K / 32;
    load_stage(0);
    if (NS > 1) load_stage(1);
    for (int s = 0; s < NS; s++) {
        if (s + 1 < NS) asm volatile("cp.async.wait_group 1;\n");
        else            asm volatile("cp.async.wait_group 0;\n");
        __syncthreads();
        int buf = s % 3;
#pragma unroll
        for (int ks = 0; ks < 2; ks++) {
            uint32_t af[4][4];
#pragma unroll
            for (int mt = 0; mt < 4; mt++)
                ldmA(af[mt], sAb[buf] + ((wm + mt * 16 + (lane & 15)) * 40 + ks * 16 + (lane >> 4) * 8) * 2);
            uint32_t bfr[4][2];
#pragma unroll
            for (int nt = 0; nt < 4; nt++)
                ldmB(bfr[nt], sBb[buf] + ((wn + nt * 8 + (lane & 7)) * 40 + ks * 16 + ((lane >> 3) & 1) * 8) * 2);
#pragma unroll
            for (int mt = 0; mt < 4; mt++)
#pragma unroll
                for (int nt = 0; nt < 4; nt++) mma_bf16(acc[mt][nt], af[mt], bfr[nt]);
        }
        if (s + 2 < NS) load_stage(s + 2);
    }

#pragma unroll
    for (int mt = 0; mt < 4; mt++)
#pragma unroll
        for (int nt = 0; nt < 4; nt++) {
            int col = n0 + wn + nt * 8 + (lane & 3) * 2;
            float b0 = bias[col], b1 = bias[col + 1];
#pragma unroll
            for (int h2 = 0; h2 < 2; h2++) {
                int gm = m0 + wm + mt * 16 + (lane >> 2) + h2 * 8;
                if (gm >= M) continue;
                float v0 = acc[mt][nt][h2 * 2 + 0] + b0;
                float v1 = acc[mt][nt][h2 * 2 + 1] + b1;
                if (EPI == 1) {
                    v0 = 0.5f * v0 * (1.f + erff(v0 * 0.70710678118654752f));
                    v1 = 0.5f * v1 * (1.f + erff(v1 * 0.70710678118654752f));
                }
                if (EPI == 2) {
                    float2 r = *(const float2*)(res + (size_t)gm * ldc + col);
                    v0 = r.x + gamma[col] * v0;
                    v1 = r.y + gamma[col + 1] * v1;
                    *(float2*)(Cf + (size_t)gm * ldc + col) = make_float2(v0, v1);
                } else {
                    __nv_bfloat162 o;
                    o.x = __float2bfloat16(v0); o.y = __float2bfloat16(v1);
                    *(__nv_bfloat162*)(Cb + (size_t)gm * ldc + col) = o;
                }
            }
        }
}

// ---------------- merged qkv + cross-kv GEMM (both EPI0, K=1024), one launch ----------------
__global__ void __launch_bounds__(256)
bgemm_qkvkv() {
    extern __shared__ bf16 smg[];
    const int t = threadIdx.x, lane = t & 31, wid = t >> 5;
    int id = blockIdx.x;
    const bf16 *A, *W; bf16* C; const float* bias;
    int m0, n0, M, Ncols, lda, ldc;
    if (id < 792) {                    // qkv: 33 x 24 tiles
        A = g_hb; W = g_wqkv; C = g_qkvb; bias = g_bias3;
        M = TM; Ncols = 3 * TE; lda = TE; ldc = 3 * TE;
        m0 = (id / 24) * 128; n0 = (id % 24) * 128;
    } else {                           // cross kv: 32 x 16 tiles
        id -= 792;
        A = g_yb; W = g_wkv; C = g_kvb; bias = g_bias2;
        M = TB * TL; Ncols = 2 * TE; lda = TE; ldc = 2 * TE;
        m0 = (id / 16) * 128; n0 = (id % 16) * 128;
    }
    uint32_t sAb[3], sBb[3];
#pragma unroll
    for (int s = 0; s < 3; s++) {
        sAb[s] = (uint32_t)__cvta_generic_to_shared(smg + s * GSTAGE);
        sBb[s] = sAb[s] + 128 * 40 * 2;
    }
    auto load_stage = [&](int s) {
        int k0 = s * 32, buf = s % 3;
#pragma unroll
        for (int i = 0; i < 2; i++) {
            int c = t + i * 256; int row = c >> 2; int cc = c & 3;
            bool v = (m0 + row) < M;
            const bf16* src = A + (size_t)(v ? m0 + row : 0) * lda + k0 + cc * 8;
            cp16(sAb[buf] + (row * 40 + cc * 8) * 2, src, v ? 16 : 0);
        }
#pragma unroll
        for (int i = 0; i < 2; i++) {
            int c = t + i * 256; int row = c >> 2; int cc = c & 3;
            bool v = (n0 + row) < Ncols;
            const bf16* src = W + (size_t)(v ? n0 + row : 0) * TE + k0 + cc * 8;
            cp16(sBb[buf] + (row * 40 + cc * 8) * 2, src, v ? 16 : 0);
        }
        cp_commit();
    };
    const int wm = (wid >> 2) * 64, wn = (wid & 3) * 32;
    float acc[4][4][4] = {};
    const int NS = TE / 32;
    load_stage(0);
    load_stage(1);
    for (int s = 0; s < NS; s++) {
        if (s + 1 < NS) asm volatile("cp.async.wait_group 1;\n");
        else            asm volatile("cp.async.wait_group 0;\n");
        __syncthreads();
        int buf = s % 3;
#pragma unroll
        for (int ks = 0; ks < 2; ks++) {
            uint32_t af[4][4];
#pragma unroll
            for (int mt = 0; mt < 4; mt++)
                ldmA(af[mt], sAb[buf] + ((wm + mt * 16 + (lane & 15)) * 40 + ks * 16 + (lane >> 4) * 8) * 2);
            uint32_t bfr[4][2];
#pragma unroll
            for (int nt = 0; nt < 4; nt++)
                ldmB(bfr[nt], sBb[buf] + ((wn + nt * 8 + (lane & 7)) * 40 + ks * 16 + ((lane >> 3) & 1) * 8) * 2);
#pragma unroll
            for (int mt = 0; mt < 4; mt++)
#pragma unroll
                for (int nt = 0; nt < 4; nt++) mma_bf16(acc[mt][nt], af[mt], bfr[nt]);
        }
        if (s + 2 < NS) load_stage(s + 2);
    }
#pragma unroll
    for (int mt = 0; mt < 4; mt++)
#pragma unroll
        for (int nt = 0; nt < 4; nt++) {
            int col = n0 + wn + nt * 8 + (lane & 3) * 2;
            float b0 = bias[col], b1 = bias[col + 1];
#pragma unroll
            for (int h2 = 0; h2 < 2; h2++) {
                int gm = m0 + wm + mt * 16 + (lane >> 2) + h2 * 8;
                if (gm >= M) continue;
                __nv_bfloat162 o;
                o.x = __float2bfloat16(acc[mt][nt][h2 * 2 + 0] + b0);
                o.y = __float2bfloat16(acc[mt][nt][h2 * 2 + 1] + b1);
                *(__nv_bfloat162*)(C + (size_t)gm * ldc + col) = o;
            }
        }
}

// ---------------- fused flash attention (fast-path softmax epilogue) ----------------
template<bool SELF>
__global__ void __launch_bounds__(256)
flash_attn(const bf16* __restrict__ qsrc, const bf16* __restrict__ kvsrc,
           const float* __restrict__ rpb, bf16* __restrict__ outp) {
    extern __shared__ char dsm[];
    bf16* Qs = (bf16*)dsm;
    bf16* Ks = Qs + FTILE;
    bf16* Vs = Ks + 2 * FTILE;
    float* tab = (float*)(dsm + 5 * FTILE * 2);

    const int t = threadIdx.x, lane = t & 31, wid = t >> 5;
    const int b = blockIdx.z >> 4, h = blockIdx.z & 15;
    const int q0 = blockIdx.x * 128;
    const int qtile = (int)blockIdx.x;
    const int Nk = SELF ? TN : TL;
    const int nkt = SELF ? (qtile + 1) : 8;
    const int ldq = SELF ? 3 * TE : TE;
    const int ldk = SELF ? 3 * TE : 2 * TE;
    const bf16* qp = SELF ? qsrc + (size_t)b * TN * 3 * TE + h * TD
                          : qsrc + (size_t)b * TN * TE + h * TD;
    const bf16* kp = SELF ? kvsrc + (size_t)b * TN * 3 * TE + TE + h * TD
                          : kvsrc + (size_t)b * TL * 2 * TE + h * TD;
    const bf16* vp = SELF ? kvsrc + (size_t)b * TN * 3 * TE + 2 * TE + h * TD
                          : kvsrc + (size_t)b * TL * 2 * TE + TE + h * TD;

    uint32_t Qb = (uint32_t)__cvta_generic_to_shared(Qs);
    uint32_t Kb[2] = {(uint32_t)__cvta_generic_to_shared(Ks),
                      (uint32_t)__cvta_generic_to_shared(Ks + FTILE)};
    uint32_t Vb[2] = {(uint32_t)__cvta_generic_to_shared(Vs),
                      (uint32_t)__cvta_generic_to_shared(Vs + FTILE)};

#pragma unroll
    for (int i = 0; i < 4; i++) {
        int c = t + i * 256; int row = c >> 3; int cc = c & 7;
        bool v = (q0 + row) < TN;
        cp16(Qb + (row * 72 + cc * 8) * 2, qp + (size_t)(v ? q0 + row : 0) * ldq + cc * 8, v ? 16 : 0);
    }
    auto load_kv = [&](int kt) {
        int buf = kt & 1;
#pragma unroll
        for (int i = 0; i < 4; i++) {
            int c = t + i * 256; int row = c >> 3; int cc = c & 7;
            int gk = kt * 128 + row;
            bool v = gk < Nk;
            const bf16* ksrc2 = kp + (size_t)(v ? gk : 0) * ldk + cc * 8;
            const bf16* vsrc2 = vp + (size_t)(v ? gk : 0) * ldk + cc * 8;
            cp16(Kb[buf] + (row * 72 + cc * 8) * 2, ksrc2, v ? 16 : 0);
            cp16(Vb[buf] + (row * 72 + cc * 8) * 2, vsrc2, v ? 16 : 0);
        }
        cp_commit();
    };
    load_kv(0);

    float b_row0 = rpb[3969 * TH + h];
    float b_col0 = SELF ? rpb[3970 * TH + h] : 0.f;
    float b_00   = SELF ? rpb[3971 * TH + h] : 0.f;

    for (int i = t; i < 63 * 63; i += 256) {
        int dq = i / 63, dr = i - dq * 63;
        tab[dq * 64 + dr] = rpb[i * TH + h];
    }

    const int wm = wid * 16;
    const int r0 = wm + (lane >> 2);
    // fq[h2] = qq + (qq & ~31)  (interior rows; fast path only used when gq >= 1)
    int fq[2];
#pragma unroll
    for (int h2 = 0; h2 < 2; h2++) {
        int qq = q0 + r0 + h2 * 8 - 1;
        fq[h2] = qq + (qq & ~31);
    }
    float m[2] = {-1e30f, -1e30f};
    float l[2] = {0.f, 0.f};
    float oacc[8][4] = {};
    uint32_t qf[4][4];

    for (int kt = 0; kt < nkt; kt++) {
        if (kt + 1 < nkt) { load_kv(kt + 1); asm volatile("cp.async.wait_group 1;\n"); }
        else              { asm volatile("cp.async.wait_group 0;\n"); }
        __syncthreads();
        int buf = kt & 1;
        if (kt == 0) {
#pragma unroll
            for (int ks = 0; ks < 4; ks++)
                ldmA(qf[ks], Qb + ((wm + (lane & 15)) * 72 + ks * 16 + (lane >> 4) * 8) * 2);
        }
        float sacc[16][4];
#pragma unroll
        for (int nt = 0; nt < 16; nt++)
#pragma unroll
            for (int e = 0; e < 4; e++) sacc[nt][e] = 0.f;
#pragma unroll
        for (int ks = 0; ks < 4; ks++) {
#pragma unroll
            for (int ntp = 0; ntp < 8; ntp++) {
                uint32_t kf[4];
                ldmA(kf, Kb[buf] + ((ntp * 16 + (lane & 15)) * 72 + ks * 16 + (lane >> 4) * 8) * 2);
                uint32_t b0[2] = {kf[0], kf[2]};
                uint32_t b1[2] = {kf[1], kf[3]};
                mma_bf16(sacc[2 * ntp],     qf[ks], b0);
                mma_bf16(sacc[2 * ntp + 1], qf[ks], b1);
            }
        }
        float mloc[2] = {-1e30f, -1e30f};
        // fast path: full chunk, no causal mask, no CLS specials, no bounds
        bool fast = (q0 != 0) && (q0 + 128 <= TN) && (!SELF || kt < qtile) && (!(SELF && kt == 0));
        if (fast) {
            const int kbase = kt * 128 + (lane & 3) * 2 - (SELF ? 1 : 0);
#pragma unroll
            for (int nt = 0; nt < 16; nt++) {
#pragma unroll
                for (int e = 0; e < 4; e++) {
                    int kk = kbase + nt * 8 + (e & 1);
                    int gkv = kk + (kk & ~31);
                    float s = sacc[nt][e] * ATT_SCALE + tab[fq[e >> 1] - gkv + 2015];
                    sacc[nt][e] = s;
                    mloc[e >> 1] = fmaxf(mloc[e >> 1], s);
                }
            }
        } else {
#pragma unroll
            for (int nt = 0; nt < 16; nt++) {
#pragma unroll
                for (int e = 0; e < 4; e++) {
                    int gk = kt * 128 + nt * 8 + (lane & 3) * 2 + (e & 1);
                    int gq = q0 + r0 + (e >> 1) * 8;
                    float s;
                    bool ok = (gq < TN) && (gk < Nk) && (!SELF || gk <= gq);
                    if (ok) {
                        float bias;
                        if (gq == 0) bias = (SELF && gk == 0) ? b_00 : b_row0;
                        else if (SELF && gk == 0) bias = b_col0;
                        else {
                            int qq = gq - 1, kk = SELF ? gk - 1 : gk;
                            int dq = ((qq >> 5) - (kk >> 5)) + 31;
                            int dr = ((qq & 31) - (kk & 31)) + 31;
                            bias = tab[dq * 64 + dr];
                        }
                        s = sacc[nt][e] * ATT_SCALE + bias;
                    } else s = -1e30f;
                    sacc[nt][e] = s;
                    mloc[e >> 1] = fmaxf(mloc[e >> 1], s);
                }
            }
        }
#pragma unroll
        for (int j = 0; j < 2; j++) {
#pragma unroll
            for (int o = 1; o < 4; o <<= 1)
                mloc[j] = fmaxf(mloc[j], __shfl_xor_sync(0xffffffffu, mloc[j], o));
            float mnew = fmaxf(m[j], mloc[j]);
            float alpha = __expf(m[j] - mnew);
            m[j] = mnew;
            l[j] *= alpha;
#pragma unroll
            for (int nt = 0; nt < 8; nt++) {
                oacc[nt][j * 2 + 0] *= alpha;
                oacc[nt][j * 2 + 1] *= alpha;
            }
        }
        float lsum[2] = {0.f, 0.f};
#pragma unroll
        for (int nt = 0; nt < 16; nt++) {
#pragma unroll
            for (int e = 0; e < 4; e++) {
                float p = __expf(sacc[nt][e] - m[e >> 1]);
                sacc[nt][e] = p;
                lsum[e >> 1] += p;
            }
        }
#pragma unroll
        for (int j = 0; j < 2; j++) {
#pragma unroll
            for (int o = 1; o < 4; o <<= 1)
                lsum[j] += __shfl_xor_sync(0xffffffffu, lsum[j], o);
            l[j] += lsum[j];
        }
#pragma unroll
        for (int kb = 0; kb < 8; kb++) {
            uint32_t pa[4];
            pa[0] = packbf(sacc[2 * kb][0],     sacc[2 * kb][1]);
            pa[1] = packbf(sacc[2 * kb][2],     sacc[2 * kb][3]);
            pa[2] = packbf(sacc[2 * kb + 1][0], sacc[2 * kb + 1][1]);
            pa[3] = packbf(sacc[2 * kb + 1][2], sacc[2 * kb + 1][3]);
#pragma unroll
            for (int ntp = 0; ntp < 4; ntp++) {
                uint32_t vf[4];
                ldmT4(vf, Vb[buf] + ((kb * 16 + (lane & 15)) * 72 + ntp * 16 + (lane >> 4) * 8) * 2);
                uint32_t vb0[2] = {vf[0], vf[1]};
                uint32_t vb1[2] = {vf[2], vf[3]};
                mma_bf16(oacc[2 * ntp],     pa, vb0);
                mma_bf16(oacc[2 * ntp + 1], pa, vb1);
            }
        }
        __syncthreads();
    }

    float inv[2] = {1.f / l[0], 1.f / l[1]};
#pragma unroll
    for (int nt = 0; nt < 8; nt++) {
        int dcol = nt * 8 + (lane & 3) * 2;
#pragma unroll
        for (int h2 = 0; h2 < 2; h2++) {
            int gq = q0 + r0 + h2 * 8;
            if (gq >= TN) continue;
            __nv_bfloat162 o;
            o.x = __float2bfloat16(oacc[nt][h2 * 2 + 0] * inv[h2]);
            o.y = __float2bfloat16(oacc[nt][h2 * 2 + 1] * inv[h2]);
            *(__nv_bfloat162*)(outp + ((size_t)b * TN + gq) * TE + h * TD + dcol) = o;
        }
    }
}

// ---------------- launch ----------------
extern "C" void kernel_launch(void* const* d_in, const int* in_sizes, int n_in,
                              void* d_out, int out_size) {
    (void)in_sizes; (void)n_in; (void)out_size;
    const float* x         = (const float*)d_in[0];
    const float* y         = (const float*)d_in[1];
    const float* n1g       = (const float*)d_in[2];
    const float* n1b       = (const float*)d_in[3];
    const float* n2g       = (const float*)d_in[4];
    const float* n2b       = (const float*)d_in[5];
    const float* n3g       = (const float*)d_in[6];
    const float* n3b       = (const float*)d_in[7];
    const float* sa_qkv_w  = (const float*)d_in[8];
    const float* sa_q_bias = (const float*)d_in[9];
    const float* sa_v_bias = (const float*)d_in[10];
    const float* sa_rpb    = (const float*)d_in[11];
    const float* sa_proj_w = (const float*)d_in[12];
    const float* sa_proj_b = (const float*)d_in[13];
    const float* ca_q_w    = (const float*)d_in[14];
    const float* ca_kv_w   = (const float*)d_in[15];
    const float* ca_q_bias = (const float*)d_in[16];
    const float* ca_v_bias = (const float*)d_in[17];
    const float* ca_rpb    = (const float*)d_in[18];
    const float* ca_proj_w = (const float*)d_in[19];
    const float* ca_proj_b = (const float*)d_in[20];
    const float* fc1_w     = (const float*)d_in[21];
    const float* fc1_b     = (const float*)d_in[22];
    const float* fc2_w     = (const float*)d_in[23];
    const float* fc2_b     = (const float*)d_in[24];
    const float* gamma1    = (const float*)d_in[25];
    const float* gamma2    = (const float*)d_in[26];
    const float* gamma3    = (const float*)d_in[27];
    float* out = (float*)d_out;

    float *p_b3, *p_b2;
    bf16 *p_hb, *p_yb, *p_qkvb, *p_kvb, *p_q2b, *p_attnb, *p_ffnb;
    bf16 *p_wqkv, *p_wkv, *p_wq, *p_wp1, *p_wp2, *p_wf1, *p_wf2;
    cudaGetSymbolAddress((void**)&p_hb, g_hb);
    cudaGetSymbolAddress((void**)&p_yb, g_yb);
    cudaGetSymbolAddress((void**)&p_qkvb, g_qkvb);
    cudaGetSymbolAddress((void**)&p_kvb, g_kvb);
    cudaGetSymbolAddress((void**)&p_q2b, g_q2b);
    cudaGetSymbolAddress((void**)&p_attnb, g_attnb);
    cudaGetSymbolAddress((void**)&p_ffnb, g_ffnb);
    cudaGetSymbolAddress((void**)&p_wqkv, g_wqkv);
    cudaGetSymbolAddress((void**)&p_wkv, g_wkv);
    cudaGetSymbolAddress((void**)&p_wq, g_wq);
    cudaGetSymbolAddress((void**)&p_wp1, g_wp1);
    cudaGetSymbolAddress((void**)&p_wp2, g_wp2);
    cudaGetSymbolAddress((void**)&p_wf1, g_wf1);
    cudaGetSymbolAddress((void**)&p_wf2, g_wf2);
    cudaGetSymbolAddress((void**)&p_b3, g_bias3);
    cudaGetSymbolAddress((void**)&p_b2, g_bias2);

    cudaFuncSetAttribute(flash_attn<true>,  cudaFuncAttributeMaxDynamicSharedMemorySize, SMEM_FLASH);
    cudaFuncSetAttribute(flash_attn<false>, cudaFuncAttributeMaxDynamicSharedMemorySize, SMEM_FLASH);
    cudaFuncSetAttribute(bgemm<0>, cudaFuncAttributeMaxDynamicSharedMemorySize, SMEM_GEMM);
    cudaFuncSetAttribute(bgemm<1>, cudaFuncAttributeMaxDynamicSharedMemorySize, SMEM_GEMM);
    cudaFuncSetAttribute(bgemm<2>, cudaFuncAttributeMaxDynamicSharedMemorySize, SMEM_GEMM);
    cudaFuncSetAttribute(bgemm_qkvkv, cudaFuncAttributeMaxDynamicSharedMemorySize, SMEM_GEMM);

    // all fp32->bf16 conversions in one launch
    f2bf_all<<<20480, 256>>>(sa_qkv_w, ca_kv_w, ca_q_w, sa_proj_w, ca_proj_w,
                             fc1_w, fc2_w, y,
                             p_wqkv, p_wkv, p_wq, p_wp1, p_wp2, p_wf1, p_wf2, p_yb);
    build_bias_kernel<<<12, 256>>>(sa_q_bias, sa_v_bias, ca_v_bias);

    // ---- self attention (qkv + cross-kv merged into one launch) ----
    ln_kernel<<<TM, 256>>>(x, n1g, n1b, p_hb);
    bgemm_qkvkv<<<1304, 256, SMEM_GEMM>>>();
    flash_attn<true><<<dim3(9, 1, 64), 256, SMEM_FLASH>>>(p_qkvb, p_qkvb, sa_rpb, p_attnb);
    bgemm<2><<<dim3(8, 33), 256, SMEM_GEMM>>>(p_attnb, TE, p_wp1, TM, TE, TE,
                                              sa_proj_b, x, gamma1, out, nullptr, TE);

    // ---- cross attention ----
    ln_kernel<<<TM, 256>>>(out, n2g, n2b, p_hb);
    bgemm<0><<<dim3(8, 33), 256, SMEM_GEMM>>>(p_hb, TE, p_wq, TM, TE, TE,
                                              ca_q_bias, nullptr, nullptr, nullptr, p_q2b, TE);
    flash_attn<false><<<dim3(9, 1, 64), 256, SMEM_FLASH>>>(p_q2b, p_kvb, ca_rpb, p_attnb);
    bgemm<2><<<dim3(8, 33), 256, SMEM_GEMM>>>(p_attnb, TE, p_wp2, TM, TE, TE,
                                              ca_proj_b, out, gamma2, out, nullptr, TE);

    // ---- FFN ----
    ln_kernel<<<TM, 256>>>(out, n3g, n3b, p_hb);
    bgemm<1><<<dim3(32, 33), 256, SMEM_GEMM>>>(p_hb, TE, p_wf1, TM, TF, TE,
                                               fc1_b, nullptr, nullptr, nullptr, p_ffnb, TF);
    bgemm<2><<<dim3(8, 33), 256, SMEM_GEMM>>>(p_ffnb, TF, p_wf2, TM, TE, TF,
                                              fc2_b, out, gamma3, out, nullptr, TE);
}

// round 16
// speedup vs baseline: 1.2226x; 1.0160x over previous
#include <cuda_runtime.h>
#include <cuda_bf16.h>
#include <math.h>
#include <stdint.h>

typedef __nv_bfloat16 bf16;

// ---------------- problem constants ----------------
constexpr int TB = 4;
constexpr int TN = 1025;
constexpr int TL = 1024;
constexpr int TE = 1024;
constexpr int TH = 16;
constexpr int TD = 64;
constexpr int TF = 4096;
constexpr int TM = TB * TN;           // 4100
constexpr float ATT_SCALE = 0.125f;

// flash smem
constexpr int FTILE = 128 * 72;
constexpr int SMEM_FLASH = 5 * FTILE * 2 + 63 * 64 * 4;   // 108288 bytes

// gemm smem: 3 stages of (A 128x40 + B 128x40) bf16
constexpr int GSTAGE = (128 + 128) * 40;                  // halfwords per stage
constexpr int SMEM_GEMM = 3 * GSTAGE * 2;                 // 61440 bytes

// ---------------- scratch ----------------
__device__ bf16  g_hb  [(size_t)TM * TE];
__device__ bf16  g_yb  [(size_t)TB * TL * TE];
__device__ bf16  g_qkvb[(size_t)TM * 3 * TE];
__device__ bf16  g_kvb [(size_t)TB * TL * 2 * TE];
__device__ bf16  g_q2b [(size_t)TM * TE];
__device__ bf16  g_attnb[(size_t)TM * TE];
__device__ bf16  g_ffnb[(size_t)TM * TF];
__device__ bf16  g_wqkv[(size_t)3 * TE * TE];
__device__ bf16  g_wkv [(size_t)2 * TE * TE];
__device__ bf16  g_wq  [(size_t)TE * TE];
__device__ bf16  g_wp1 [(size_t)TE * TE];
__device__ bf16  g_wp2 [(size_t)TE * TE];
__device__ bf16  g_wf1 [(size_t)TF * TE];
__device__ bf16  g_wf2 [(size_t)TE * TF];
__device__ float g_bias3[3 * TE];
__device__ float g_bias2[2 * TE];

// ---------------- PTX helpers ----------------
__device__ __forceinline__ void cp16(uint32_t smem, const void* gmem, int bytes) {
    asm volatile("cp.async.cg.shared.global [%0], [%1], 16, %2;\n"
                 :: "r"(smem), "l"(gmem), "r"(bytes));
}
__device__ __forceinline__ void cp_commit() { asm volatile("cp.async.commit_group;\n"); }

__device__ __forceinline__ void ldmA(uint32_t* a, uint32_t addr) {
    asm volatile("ldmatrix.sync.aligned.m8n8.x4.shared.b16 {%0,%1,%2,%3}, [%4];\n"
                 : "=r"(a[0]), "=r"(a[1]), "=r"(a[2]), "=r"(a[3]) : "r"(addr));
}
__device__ __forceinline__ void ldmB(uint32_t* b, uint32_t addr) {
    asm volatile("ldmatrix.sync.aligned.m8n8.x2.shared.b16 {%0,%1}, [%2];\n"
                 : "=r"(b[0]), "=r"(b[1]) : "r"(addr));
}
__device__ __forceinline__ void ldmT4(uint32_t* b, uint32_t addr) {
    asm volatile("ldmatrix.sync.aligned.m8n8.x4.trans.shared.b16 {%0,%1,%2,%3}, [%4];\n"
                 : "=r"(b[0]), "=r"(b[1]), "=r"(b[2]), "=r"(b[3]) : "r"(addr));
}
__device__ __forceinline__ void mma_bf16(float* d, const uint32_t* a, const uint32_t* b) {
    asm volatile("mma.sync.aligned.m16n8k16.row.col.f32.bf16.bf16.f32 "
                 "{%0,%1,%2,%3}, {%4,%5,%6,%7}, {%8,%9}, {%0,%1,%2,%3};\n"
                 : "+f"(d[0]), "+f"(d[1]), "+f"(d[2]), "+f"(d[3])
                 : "r"(a[0]), "r"(a[1]), "r"(a[2]), "r"(a[3]), "r"(b[0]), "r"(b[1]));
}
__device__ __forceinline__ uint32_t packbf(float x, float y) {
    __nv_bfloat162 p = __floats2bfloat162_rn(x, y);
    return *(uint32_t*)&p;
}

// ---------------- reductions ----------------
__device__ __forceinline__ float block_sum(float v) {
    __shared__ float sm[32];
    int lane = threadIdx.x & 31, wid = threadIdx.x >> 5;
#pragma unroll
    for (int o = 16; o > 0; o >>= 1) v += __shfl_xor_sync(0xffffffffu, v, o);
    if (lane == 0) sm[wid] = v;
    __syncthreads();
    if (wid == 0) {
        v = (lane < (int)(blockDim.x >> 5)) ? sm[lane] : 0.f;
#pragma unroll
        for (int o = 16; o > 0; o >>= 1) v += __shfl_xor_sync(0xffffffffu, v, o);
        if (lane == 0) sm[0] = v;
    }
    __syncthreads();
    float r = sm[0];
    __syncthreads();
    return r;
}
__device__ __forceinline__ float block_maxv(float v) {
    __shared__ float smx[32];
    int lane = threadIdx.x & 31, wid = threadIdx.x >> 5;
#pragma unroll
    for (int o = 16; o > 0; o >>= 1) v = fmaxf(v, __shfl_xor_sync(0xffffffffu, v, o));
    if (lane == 0) smx[wid] = v;
    __syncthreads();
    if (wid == 0) {
        v = (lane < (int)(blockDim.x >> 5)) ? smx[lane] : -3.4e38f;
#pragma unroll
        for (int o = 16; o > 0; o >>= 1) v = fmaxf(v, __shfl_xor_sync(0xffffffffu, v, o));
        if (lane == 0) smx[0] = v;
    }
    __syncthreads();
    float r = smx[0];
    __syncthreads();
    return r;
}

// ---------------- fused fp32->bf16 conversion (one launch) ----------------
__global__ void f2bf_all(const float* __restrict__ s0, const float* __restrict__ s1,
                         const float* __restrict__ s2, const float* __restrict__ s3,
                         const float* __restrict__ s4, const float* __restrict__ s5,
                         const float* __restrict__ s6, const float* __restrict__ s7,
                         bf16* d0, bf16* d1, bf16* d2, bf16* d3,
                         bf16* d4, bf16* d5, bf16* d6, bf16* d7) {
    long i = (long)blockIdx.x * 256 + threadIdx.x;   // vec4 index
    const float* s; bf16* d;
    if (i < 786432)                    { s = s0; d = d0; }
    else if ((i -= 786432) < 524288)   { s = s1; d = d1; }
    else if ((i -= 524288) < 262144)   { s = s2; d = d2; }
    else if ((i -= 262144) < 262144)   { s = s3; d = d3; }
    else if ((i -= 262144) < 262144)   { s = s4; d = d4; }
    else if ((i -= 262144) < 1048576)  { s = s5; d = d5; }
    else if ((i -= 1048576) < 1048576) { s = s6; d = d6; }
    else { i -= 1048576;                 s = s7; d = d7; }
    float4 v = ((const float4*)s)[i];
    __nv_bfloat162 p0, p1;
    p0.x = __float2bfloat16(v.x); p0.y = __float2bfloat16(v.y);
    p1.x = __float2bfloat16(v.z); p1.y = __float2bfloat16(v.w);
    __nv_bfloat162* o = (__nv_bfloat162*)(d + i * 4);
    o[0] = p0; o[1] = p1;
}

__global__ void build_bias_kernel(const float* __restrict__ saq,
                                  const float* __restrict__ sav,
                                  const float* __restrict__ cav) {
    int i = blockIdx.x * 256 + threadIdx.x;
    if (i < 3 * TE)
        g_bias3[i] = (i < TE) ? saq[i] : ((i < 2 * TE) ? 0.f : sav[i - 2 * TE]);
    if (i < 2 * TE)
        g_bias2[i] = (i < TE) ? 0.f : cav[i - TE];
}

// LayerNorm: fp32 in -> bf16 out
__global__ void ln_kernel(const float* __restrict__ x, const float* __restrict__ g,
                          const float* __restrict__ b, bf16* __restrict__ out) {
    int row = blockIdx.x;
    int t = threadIdx.x;
    float4 v = ((const float4*)(x + (size_t)row * TE))[t];
    float mean = block_sum(v.x + v.y + v.z + v.w) * (1.f / TE);
    float dx = v.x - mean, dy = v.y - mean, dz = v.z - mean, dw = v.w - mean;
    float var = block_sum(dx * dx + dy * dy + dz * dz + dw * dw) * (1.f / TE);
    float rstd = rsqrtf(var + 1e-5f);
    float4 gg = ((const float4*)g)[t];
    float4 bb = ((const float4*)b)[t];
    __nv_bfloat162 p0, p1;
    p0.x = __float2bfloat16(dx * rstd * gg.x + bb.x);
    p0.y = __float2bfloat16(dy * rstd * gg.y + bb.y);
    p1.x = __float2bfloat16(dz * rstd * gg.z + bb.z);
    p1.y = __float2bfloat16(dw * rstd * gg.w + bb.w);
    __nv_bfloat162* o = (__nv_bfloat162*)(out + (size_t)row * TE);
    o[2 * t] = p0; o[2 * t + 1] = p1;
}

// ---------------- bf16 tensor-core GEMM (R11-exact) ----------------
template<int EPI>
__global__ void __launch_bounds__(256)
bgemm(const bf16* __restrict__ A, int lda,
      const bf16* __restrict__ W,
      int M, int Ncols, int K,
      const float* __restrict__ bias,
      const float* __restrict__ res,
      const float* __restrict__ gamma,
      float* __restrict__ Cf, bf16* __restrict__ Cb, int ldc) {
    extern __shared__ bf16 smg[];
    const int t = threadIdx.x, lane = t & 31, wid = t >> 5;
    const int m0 = blockIdx.y * 128, n0 = blockIdx.x * 128;
    uint32_t sAb[3], sBb[3];
#pragma unroll
    for (int s = 0; s < 3; s++) {
        sAb[s] = (uint32_t)__cvta_generic_to_shared(smg + s * GSTAGE);
        sBb[s] = sAb[s] + 128 * 40 * 2;
    }

    auto load_stage = [&](int s) {
        int k0 = s * 32, buf = s % 3;
#pragma unroll
        for (int i = 0; i < 2; i++) {
            int c = t + i * 256; int row = c >> 2; int cc = c & 3;
            bool v = (m0 + row) < M;
            const bf16* src = A + (size_t)(v ? m0 + row : 0) * lda + k0 + cc * 8;
            cp16(sAb[buf] + (row * 40 + cc * 8) * 2, src, v ? 16 : 0);
        }
#pragma unroll
        for (int i = 0; i < 2; i++) {
            int c = t + i * 256; int row = c >> 2; int cc = c & 3;
            bool v = (n0 + row) < Ncols;
            const bf16* src = W + (size_t)(v ? n0 + row : 0) * K + k0 + cc * 8;
            cp16(sBb[buf] + (row * 40 + cc * 8) * 2, src, v ? 16 : 0);
        }
        cp_commit();
    };

    const int wm = (wid >> 2) * 64, wn = (wid & 3) * 32;
    float acc[4][4][4] = {};
    const int NS = K / 32;
    load_stage(0);
    if (NS > 1) load_stage(1);
    for (int s = 0; s < NS; s++) {
        if (s + 1 < NS) asm volatile("cp.async.wait_group 1;\n");
        else            asm volatile("cp.async.wait_group 0;\n");
        __syncthreads();
        int buf = s % 3;
#pragma unroll
        for (int ks = 0; ks < 2; ks++) {
            uint32_t af[4][4];
#pragma unroll
            for (int mt = 0; mt < 4; mt++)
                ldmA(af[mt], sAb[buf] + ((wm + mt * 16 + (lane & 15)) * 40 + ks * 16 + (lane >> 4) * 8) * 2);
            uint32_t bfr[4][2];
#pragma unroll
            for (int nt = 0; nt < 4; nt++)
                ldmB(bfr[nt], sBb[buf] + ((wn + nt * 8 + (lane & 7)) * 40 + ks * 16 + ((lane >> 3) & 1) * 8) * 2);
#pragma unroll
            for (int mt = 0; mt < 4; mt++)
#pragma unroll
                for (int nt = 0; nt < 4; nt++) mma_bf16(acc[mt][nt], af[mt], bfr[nt]);
        }
        if (s + 2 < NS) load_stage(s + 2);
    }

#pragma unroll
    for (int mt = 0; mt < 4; mt++)
#pragma unroll
        for (int nt = 0; nt < 4; nt++) {
            int col = n0 + wn + nt * 8 + (lane & 3) * 2;
            float b0 = bias[col], b1 = bias[col + 1];
#pragma unroll
            for (int h2 = 0; h2 < 2; h2++) {
                int gm = m0 + wm + mt * 16 + (lane >> 2) + h2 * 8;
                if (gm >= M) continue;
                float v0 = acc[mt][nt][h2 * 2 + 0] + b0;
                float v1 = acc[mt][nt][h2 * 2 + 1] + b1;
                if (EPI == 1) {
                    v0 = 0.5f * v0 * (1.f + erff(v0 * 0.70710678118654752f));
                    v1 = 0.5f * v1 * (1.f + erff(v1 * 0.70710678118654752f));
                }
                if (EPI == 2) {
                    float2 r = *(const float2*)(res + (size_t)gm * ldc + col);
                    v0 = r.x + gamma[col] * v0;
                    v1 = r.y + gamma[col + 1] * v1;
                    *(float2*)(Cf + (size_t)gm * ldc + col) = make_float2(v0, v1);
                } else {
                    __nv_bfloat162 o;
                    o.x = __float2bfloat16(v0); o.y = __float2bfloat16(v1);
                    *(__nv_bfloat162*)(Cb + (size_t)gm * ldc + col) = o;
                }
            }
        }
}

// ---------------- merged qkv + cross-kv GEMM (both EPI0, K=1024), one launch ----------------
__global__ void __launch_bounds__(256)
bgemm_qkvkv() {
    extern __shared__ bf16 smg[];
    const int t = threadIdx.x, lane = t & 31, wid = t >> 5;
    int id = blockIdx.x;
    const bf16 *A, *W; bf16* C; const float* bias;
    int m0, n0, M, Ncols, lda, ldc;
    if (id < 792) {                    // qkv: 33 x 24 tiles
        A = g_hb; W = g_wqkv; C = g_qkvb; bias = g_bias3;
        M = TM; Ncols = 3 * TE; lda = TE; ldc = 3 * TE;
        m0 = (id / 24) * 128; n0 = (id % 24) * 128;
    } else {                           // cross kv: 32 x 16 tiles
        id -= 792;
        A = g_yb; W = g_wkv; C = g_kvb; bias = g_bias2;
        M = TB * TL; Ncols = 2 * TE; lda = TE; ldc = 2 * TE;
        m0 = (id / 16) * 128; n0 = (id % 16) * 128;
    }
    uint32_t sAb[3], sBb[3];
#pragma unroll
    for (int s = 0; s < 3; s++) {
        sAb[s] = (uint32_t)__cvta_generic_to_shared(smg + s * GSTAGE);
        sBb[s] = sAb[s] + 128 * 40 * 2;
    }
    auto load_stage = [&](int s) {
        int k0 = s * 32, buf = s % 3;
#pragma unroll
        for (int i = 0; i < 2; i++) {
            int c = t + i * 256; int row = c >> 2; int cc = c & 3;
            bool v = (m0 + row) < M;
            const bf16* src = A + (size_t)(v ? m0 + row : 0) * lda + k0 + cc * 8;
            cp16(sAb[buf] + (row * 40 + cc * 8) * 2, src, v ? 16 : 0);
        }
#pragma unroll
        for (int i = 0; i < 2; i++) {
            int c = t + i * 256; int row = c >> 2; int cc = c & 3;
            bool v = (n0 + row) < Ncols;
            const bf16* src = W + (size_t)(v ? n0 + row : 0) * TE + k0 + cc * 8;
            cp16(sBb[buf] + (row * 40 + cc * 8) * 2, src, v ? 16 : 0);
        }
        cp_commit();
    };
    const int wm = (wid >> 2) * 64, wn = (wid & 3) * 32;
    float acc[4][4][4] = {};
    const int NS = TE / 32;
    load_stage(0);
    load_stage(1);
    for (int s = 0; s < NS; s++) {
        if (s + 1 < NS) asm volatile("cp.async.wait_group 1;\n");
        else            asm volatile("cp.async.wait_group 0;\n");
        __syncthreads();
        int buf = s % 3;
#pragma unroll
        for (int ks = 0; ks < 2; ks++) {
            uint32_t af[4][4];
#pragma unroll
            for (int mt = 0; mt < 4; mt++)
                ldmA(af[mt], sAb[buf] + ((wm + mt * 16 + (lane & 15)) * 40 + ks * 16 + (lane >> 4) * 8) * 2);
            uint32_t bfr[4][2];
#pragma unroll
            for (int nt = 0; nt < 4; nt++)
                ldmB(bfr[nt], sBb[buf] + ((wn + nt * 8 + (lane & 7)) * 40 + ks * 16 + ((lane >> 3) & 1) * 8) * 2);
#pragma unroll
            for (int mt = 0; mt < 4; mt++)
#pragma unroll
                for (int nt = 0; nt < 4; nt++) mma_bf16(acc[mt][nt], af[mt], bfr[nt]);
        }
        if (s + 2 < NS) load_stage(s + 2);
    }
#pragma unroll
    for (int mt = 0; mt < 4; mt++)
#pragma unroll
        for (int nt = 0; nt < 4; nt++) {
            int col = n0 + wn + nt * 8 + (lane & 3) * 2;
            float b0 = bias[col], b1 = bias[col + 1];
#pragma unroll
            for (int h2 = 0; h2 < 2; h2++) {
                int gm = m0 + wm + mt * 16 + (lane >> 2) + h2 * 8;
                if (gm >= M) continue;
                __nv_bfloat162 o;
                o.x = __float2bfloat16(acc[mt][nt][h2 * 2 + 0] + b0);
                o.y = __float2bfloat16(acc[mt][nt][h2 * 2 + 1] + b1);
                *(__nv_bfloat162*)(C + (size_t)gm * ldc + col) = o;
            }
        }
}

// ---------------- last-row (q=1024) attention: one CTA per (b,h) ----------------
template<bool SELF>
__global__ void __launch_bounds__(256)
lastrow_attn(const bf16* __restrict__ qsrc, const bf16* __restrict__ kvsrc,
             const float* __restrict__ rpb, bf16* __restrict__ outp) {
    __shared__ float qs[64];
    __shared__ float sc[1025];
    __shared__ float part[256];
    const int t = threadIdx.x;
    const int b = blockIdx.x >> 4, h = blockIdx.x & 15;
    const int Nk = SELF ? TN : TL;
    const int ldq = SELF ? 3 * TE : TE;
    const int ldk = SELF ? 3 * TE : 2 * TE;
    const bf16* qp = SELF ? qsrc + (size_t)b * TN * 3 * TE + h * TD
                          : qsrc + (size_t)b * TN * TE + h * TD;
    const bf16* kp = SELF ? kvsrc + (size_t)b * TN * 3 * TE + TE + h * TD
                          : kvsrc + (size_t)b * TL * 2 * TE + h * TD;
    const bf16* vp = SELF ? kvsrc + (size_t)b * TN * 3 * TE + 2 * TE + h * TD
                          : kvsrc + (size_t)b * TL * 2 * TE + TE + h * TD;

    if (t < 64) qs[t] = __bfloat162float(qp[(size_t)1024 * ldq + t]);
    __syncthreads();

    float mx = -3.4e38f;
    for (int j = t; j < Nk; j += 256) {
        const __nv_bfloat162* k2 = (const __nv_bfloat162*)(kp + (size_t)j * ldk);
        float dot = 0.f;
#pragma unroll
        for (int u = 0; u < 32; u++) {
            float2 kf = __bfloat1622float2(k2[u]);
            dot = fmaf(qs[2 * u], kf.x, dot);
            dot = fmaf(qs[2 * u + 1], kf.y, dot);
        }
        int idx;
        if (SELF && j == 0) idx = 3970;
        else {
            int kk = SELF ? j - 1 : j;              // qq = 1023: dq=62-(kk>>5), dr=62-(kk&31)
            idx = (62 - (kk >> 5)) * 63 + 62 - (kk & 31);
        }
        float s = dot * ATT_SCALE + rpb[idx * TH + h];
        sc[j] = s;
        mx = fmaxf(mx, s);
    }
    mx = block_maxv(mx);
    float ls = 0.f;
    for (int j = t; j < Nk; j += 256) {
        float p = __expf(sc[j] - mx);
        sc[j] = p;
        ls += p;
    }
    float l = block_sum(ls);
    float inv = 1.f / l;

    int d = t & 63, grp = t >> 6;
    float acc = 0.f;
    for (int j = grp; j < Nk; j += 4)
        acc = fmaf(sc[j], __bfloat162float(vp[(size_t)j * ldk + d]), acc);
    part[t] = acc;
    __syncthreads();
    if (t < 64) {
        float o = (part[t] + part[64 + t] + part[128 + t] + part[192 + t]) * inv;
        outp[((size_t)b * TN + 1024) * TE + h * TD + t] = __float2bfloat16(o);
    }
}

// ---------------- fused flash attention (8 q-tiles, rows 0..1023; heavy-first for self) ----------------
template<bool SELF>
__global__ void __launch_bounds__(256)
flash_attn(const bf16* __restrict__ qsrc, const bf16* __restrict__ kvsrc,
           const float* __restrict__ rpb, bf16* __restrict__ outp) {
    extern __shared__ char dsm[];
    bf16* Qs = (bf16*)dsm;
    bf16* Ks = Qs + FTILE;
    bf16* Vs = Ks + 2 * FTILE;
    float* tab = (float*)(dsm + 5 * FTILE * 2);

    const int t = threadIdx.x, lane = t & 31, wid = t >> 5;
    const int b = blockIdx.z >> 4, h = blockIdx.z & 15;
    const int qtile = SELF ? (7 - (int)blockIdx.x) : (int)blockIdx.x;   // heavy tiles first (self)
    const int q0 = qtile * 128;
    const int Nk = SELF ? TN : TL;      // kv bound for guards; chunks below never exceed 1024 rows
    const int nkt = SELF ? (qtile + 1) : 8;
    const int ldq = SELF ? 3 * TE : TE;
    const int ldk = SELF ? 3 * TE : 2 * TE;
    const bf16* qp = SELF ? qsrc + (size_t)b * TN * 3 * TE + h * TD
                          : qsrc + (size_t)b * TN * TE + h * TD;
    const bf16* kp = SELF ? kvsrc + (size_t)b * TN * 3 * TE + TE + h * TD
                          : kvsrc + (size_t)b * TL * 2 * TE + h * TD;
    const bf16* vp = SELF ? kvsrc + (size_t)b * TN * 3 * TE + 2 * TE + h * TD
                          : kvsrc + (size_t)b * TL * 2 * TE + TE + h * TD;

    uint32_t Qb = (uint32_t)__cvta_generic_to_shared(Qs);
    uint32_t Kb[2] = {(uint32_t)__cvta_generic_to_shared(Ks),
                      (uint32_t)__cvta_generic_to_shared(Ks + FTILE)};
    uint32_t Vb[2] = {(uint32_t)__cvta_generic_to_shared(Vs),
                      (uint32_t)__cvta_generic_to_shared(Vs + FTILE)};

#pragma unroll
    for (int i = 0; i < 4; i++) {
        int c = t + i * 256; int row = c >> 3; int cc = c & 7;
        cp16(Qb + (row * 72 + cc * 8) * 2, qp + (size_t)(q0 + row) * ldq + cc * 8, 16);
    }
    auto load_kv = [&](int kt) {
        int buf = kt & 1;
#pragma unroll
        for (int i = 0; i < 4; i++) {
            int c = t + i * 256; int row = c >> 3; int cc = c & 7;
            int gk = kt * 128 + row;
            bool v = gk < Nk;
            const bf16* ksrc2 = kp + (size_t)(v ? gk : 0) * ldk + cc * 8;
            const bf16* vsrc2 = vp + (size_t)(v ? gk : 0) * ldk + cc * 8;
            cp16(Kb[buf] + (row * 72 + cc * 8) * 2, ksrc2, v ? 16 : 0);
            cp16(Vb[buf] + (row * 72 + cc * 8) * 2, vsrc2, v ? 16 : 0);
        }
        cp_commit();
    };
    load_kv(0);

    float b_row0 = rpb[3969 * TH + h];
    float b_col0 = SELF ? rpb[3970 * TH + h] : 0.f;
    float b_00   = SELF ? rpb[3971 * TH + h] : 0.f;

    for (int i = t; i < 63 * 63; i += 256) {
        int dq = i / 63, dr = i - dq * 63;
        tab[dq * 64 + dr] = rpb[i * TH + h];
    }

    const int wm = wid * 16;
    const int r0 = wm + (lane >> 2);
    int fq[2];
#pragma unroll
    for (int h2 = 0; h2 < 2; h2++) {
        int qq = q0 + r0 + h2 * 8 - 1;
        fq[h2] = qq + (qq & ~31);
    }
    float m[2] = {-1e30f, -1e30f};
    float l[2] = {0.f, 0.f};
    float oacc[8][4] = {};
    uint32_t qf[4][4];

    for (int kt = 0; kt < nkt; kt++) {
        if (kt + 1 < nkt) { load_kv(kt + 1); asm volatile("cp.async.wait_group 1;\n"); }
        else              { asm volatile("cp.async.wait_group 0;\n"); }
        __syncthreads();
        int buf = kt & 1;
        if (kt == 0) {
#pragma unroll
            for (int ks = 0; ks < 4; ks++)
                ldmA(qf[ks], Qb + ((wm + (lane & 15)) * 72 + ks * 16 + (lane >> 4) * 8) * 2);
        }
        float sacc[16][4];
#pragma unroll
        for (int nt = 0; nt < 16; nt++)
#pragma unroll
            for (int e = 0; e < 4; e++) sacc[nt][e] = 0.f;
#pragma unroll
        for (int ks = 0; ks < 4; ks++) {
#pragma unroll
            for (int ntp = 0; ntp < 8; ntp++) {
                uint32_t kf[4];
                ldmA(kf, Kb[buf] + ((ntp * 16 + (lane & 15)) * 72 + ks * 16 + (lane >> 4) * 8) * 2);
                uint32_t b0[2] = {kf[0], kf[2]};
                uint32_t b1[2] = {kf[1], kf[3]};
                mma_bf16(sacc[2 * ntp],     qf[ks], b0);
                mma_bf16(sacc[2 * ntp + 1], qf[ks], b1);
            }
        }
        float mloc[2] = {-1e30f, -1e30f};
        bool fast = (q0 != 0) && (!SELF || kt < qtile) && (!(SELF && kt == 0));
        if (fast) {
            const int kbase = kt * 128 + (lane & 3) * 2 - (SELF ? 1 : 0);
#pragma unroll
            for (int nt = 0; nt < 16; nt++) {
#pragma unroll
                for (int e = 0; e < 4; e++) {
                    int kk = kbase + nt * 8 + (e & 1);
                    int gkv = kk + (kk & ~31);
                    float s = sacc[nt][e] * ATT_SCALE + tab[fq[e >> 1] - gkv + 2015];
                    sacc[nt][e] = s;
                    mloc[e >> 1] = fmaxf(mloc[e >> 1], s);
                }
            }
        } else {
#pragma unroll
            for (int nt = 0; nt < 16; nt++) {
#pragma unroll
                for (int e = 0; e < 4; e++) {
                    int gk = kt * 128 + nt * 8 + (lane & 3) * 2 + (e & 1);
                    int gq = q0 + r0 + (e >> 1) * 8;
                    float s;
                    bool ok = (gk < Nk) && (!SELF || gk <= gq);
                    if (ok) {
                        float bias;
                        if (gq == 0) bias = (SELF && gk == 0) ? b_00 : b_row0;
                        else if (SELF && gk == 0) bias = b_col0;
                        else {
                            int qq = gq - 1, kk = SELF ? gk - 1 : gk;
                            int dq = ((qq >> 5) - (kk >> 5)) + 31;
                            int dr = ((qq & 31) - (kk & 31)) + 31;
                            bias = tab[dq * 64 + dr];
                        }
                        s = sacc[nt][e] * ATT_SCALE + bias;
                    } else s = -1e30f;
                    sacc[nt][e] = s;
                    mloc[e >> 1] = fmaxf(mloc[e >> 1], s);
                }
            }
        }
#pragma unroll
        for (int j = 0; j < 2; j++) {
#pragma unroll
            for (int o = 1; o < 4; o <<= 1)
                mloc[j] = fmaxf(mloc[j], __shfl_xor_sync(0xffffffffu, mloc[j], o));
            float mnew = fmaxf(m[j], mloc[j]);
            float alpha = __expf(m[j] - mnew);
            m[j] = mnew;
            l[j] *= alpha;
#pragma unroll
            for (int nt = 0; nt < 8; nt++) {
                oacc[nt][j * 2 + 0] *= alpha;
                oacc[nt][j * 2 + 1] *= alpha;
            }
        }
        float lsum[2] = {0.f, 0.f};
#pragma unroll
        for (int nt = 0; nt < 16; nt++) {
#pragma unroll
            for (int e = 0; e < 4; e++) {
                float p = __expf(sacc[nt][e] - m[e >> 1]);
                sacc[nt][e] = p;
                lsum[e >> 1] += p;
            }
        }
#pragma unroll
        for (int j = 0; j < 2; j++) {
#pragma unroll
            for (int o = 1; o < 4; o <<= 1)
                lsum[j] += __shfl_xor_sync(0xffffffffu, lsum[j], o);
            l[j] += lsum[j];
        }
#pragma unroll
        for (int kb = 0; kb < 8; kb++) {
            uint32_t pa[4];
            pa[0] = packbf(sacc[2 * kb][0],     sacc[2 * kb][1]);
            pa[1] = packbf(sacc[2 * kb][2],     sacc[2 * kb][3]);
            pa[2] = packbf(sacc[2 * kb + 1][0], sacc[2 * kb + 1][1]);
            pa[3] = packbf(sacc[2 * kb + 1][2], sacc[2 * kb + 1][3]);
#pragma unroll
            for (int ntp = 0; ntp < 4; ntp++) {
                uint32_t vf[4];
                ldmT4(vf, Vb[buf] + ((kb * 16 + (lane & 15)) * 72 + ntp * 16 + (lane >> 4) * 8) * 2);
                uint32_t vb0[2] = {vf[0], vf[1]};
                uint32_t vb1[2] = {vf[2], vf[3]};
                mma_bf16(oacc[2 * ntp],     pa, vb0);
                mma_bf16(oacc[2 * ntp + 1], pa, vb1);
            }
        }
        __syncthreads();
    }

    float inv[2] = {1.f / l[0], 1.f / l[1]};
#pragma unroll
    for (int nt = 0; nt < 8; nt++) {
        int dcol = nt * 8 + (lane & 3) * 2;
#pragma unroll
        for (int h2 = 0; h2 < 2; h2++) {
            int gq = q0 + r0 + h2 * 8;
            __nv_bfloat162 o;
            o.x = __float2bfloat16(oacc[nt][h2 * 2 + 0] * inv[h2]);
            o.y = __float2bfloat16(oacc[nt][h2 * 2 + 1] * inv[h2]);
            *(__nv_bfloat162*)(outp + ((size_t)b * TN + gq) * TE + h * TD + dcol) = o;
        }
    }
}

// ---------------- launch ----------------
extern "C" void kernel_launch(void* const* d_in, const int* in_sizes, int n_in,
                              void* d_out, int out_size) {
    (void)in_sizes; (void)n_in; (void)out_size;
    const float* x         = (const float*)d_in[0];
    const float* y         = (const float*)d_in[1];
    const float* n1g       = (const float*)d_in[2];
    const float* n1b       = (const float*)d_in[3];
    const float* n2g       = (const float*)d_in[4];
    const float* n2b       = (const float*)d_in[5];
    const float* n3g       = (const float*)d_in[6];
    const float* n3b       = (const float*)d_in[7];
    const float* sa_qkv_w  = (const float*)d_in[8];
    const float* sa_q_bias = (const float*)d_in[9];
    const float* sa_v_bias = (const float*)d_in[10];
    const float* sa_rpb    = (const float*)d_in[11];
    const float* sa_proj_w = (const float*)d_in[12];
    const float* sa_proj_b = (const float*)d_in[13];
    const float* ca_q_w    = (const float*)d_in[14];
    const float* ca_kv_w   = (const float*)d_in[15];
    const float* ca_q_bias = (const float*)d_in[16];
    const float* ca_v_bias = (const float*)d_in[17];
    const float* ca_rpb    = (const float*)d_in[18];
    const float* ca_proj_w = (const float*)d_in[19];
    const float* ca_proj_b = (const float*)d_in[20];
    const float* fc1_w     = (const float*)d_in[21];
    const float* fc1_b     = (const float*)d_in[22];
    const float* fc2_w     = (const float*)d_in[23];
    const float* fc2_b     = (const float*)d_in[24];
    const float* gamma1    = (const float*)d_in[25];
    const float* gamma2    = (const float*)d_in[26];
    const float* gamma3    = (const float*)d_in[27];
    float* out = (float*)d_out;

    float *p_b3, *p_b2;
    bf16 *p_hb, *p_yb, *p_qkvb, *p_kvb, *p_q2b, *p_attnb, *p_ffnb;
    bf16 *p_wqkv, *p_wkv, *p_wq, *p_wp1, *p_wp2, *p_wf1, *p_wf2;
    cudaGetSymbolAddress((void**)&p_hb, g_hb);
    cudaGetSymbolAddress((void**)&p_yb, g_yb);
    cudaGetSymbolAddress((void**)&p_qkvb, g_qkvb);
    cudaGetSymbolAddress((void**)&p_kvb, g_kvb);
    cudaGetSymbolAddress((void**)&p_q2b, g_q2b);
    cudaGetSymbolAddress((void**)&p_attnb, g_attnb);
    cudaGetSymbolAddress((void**)&p_ffnb, g_ffnb);
    cudaGetSymbolAddress((void**)&p_wqkv, g_wqkv);
    cudaGetSymbolAddress((void**)&p_wkv, g_wkv);
    cudaGetSymbolAddress((void**)&p_wq, g_wq);
    cudaGetSymbolAddress((void**)&p_wp1, g_wp1);
    cudaGetSymbolAddress((void**)&p_wp2, g_wp2);
    cudaGetSymbolAddress((void**)&p_wf1, g_wf1);
    cudaGetSymbolAddress((void**)&p_wf2, g_wf2);
    cudaGetSymbolAddress((void**)&p_b3, g_bias3);
    cudaGetSymbolAddress((void**)&p_b2, g_bias2);

    cudaFuncSetAttribute(flash_attn<true>,  cudaFuncAttributeMaxDynamicSharedMemorySize, SMEM_FLASH);
    cudaFuncSetAttribute(flash_attn<false>, cudaFuncAttributeMaxDynamicSharedMemorySize, SMEM_FLASH);
    cudaFuncSetAttribute(bgemm<0>, cudaFuncAttributeMaxDynamicSharedMemorySize, SMEM_GEMM);
    cudaFuncSetAttribute(bgemm<1>, cudaFuncAttributeMaxDynamicSharedMemorySize, SMEM_GEMM);
    cudaFuncSetAttribute(bgemm<2>, cudaFuncAttributeMaxDynamicSharedMemorySize, SMEM_GEMM);
    cudaFuncSetAttribute(bgemm_qkvkv, cudaFuncAttributeMaxDynamicSharedMemorySize, SMEM_GEMM);

    // all fp32->bf16 conversions in one launch
    f2bf_all<<<20480, 256>>>(sa_qkv_w, ca_kv_w, ca_q_w, sa_proj_w, ca_proj_w,
                             fc1_w, fc2_w, y,
                             p_wqkv, p_wkv, p_wq, p_wp1, p_wp2, p_wf1, p_wf2, p_yb);
    build_bias_kernel<<<12, 256>>>(sa_q_bias, sa_v_bias, ca_v_bias);

    // ---- self attention (qkv + cross-kv merged into one launch) ----
    ln_kernel<<<TM, 256>>>(x, n1g, n1b, p_hb);
    bgemm_qkvkv<<<1304, 256, SMEM_GEMM>>>();
    flash_attn<true><<<dim3(8, 1, 64), 256, SMEM_FLASH>>>(p_qkvb, p_qkvb, sa_rpb, p_attnb);
    lastrow_attn<true><<<64, 256>>>(p_qkvb, p_qkvb, sa_rpb, p_attnb);
    bgemm<2><<<dim3(8, 33), 256, SMEM_GEMM>>>(p_attnb, TE, p_wp1, TM, TE, TE,
                                              sa_proj_b, x, gamma1, out, nullptr, TE);

    // ---- cross attention ----
    ln_kernel<<<TM, 256>>>(out, n2g, n2b, p_hb);
    bgemm<0><<<dim3(8, 33), 256, SMEM_GEMM>>>(p_hb, TE, p_wq, TM, TE, TE,
                                              ca_q_bias, nullptr, nullptr, nullptr, p_q2b, TE);
    flash_attn<false><<<dim3(8, 1, 64), 256, SMEM_FLASH>>>(p_q2b, p_kvb, ca_rpb, p_attnb);
    lastrow_attn<false><<<64, 256>>>(p_q2b, p_kvb, ca_rpb, p_attnb);
    bgemm<2><<<dim3(8, 33), 256, SMEM_GEMM>>>(p_attnb, TE, p_wp2, TM, TE, TE,
                                              ca_proj_b, out, gamma2, out, nullptr, TE);

    // ---- FFN ----
    ln_kernel<<<TM, 256>>>(out, n3g, n3b, p_hb);
    bgemm<1><<<dim3(32, 33), 256, SMEM_GEMM>>>(p_hb, TE, p_wf1, TM, TF, TE,
                                               fc1_b, nullptr, nullptr, nullptr, p_ffnb, TF);
    bgemm<2><<<dim3(8, 33), 256, SMEM_GEMM>>>(p_ffnb, TF, p_wf2, TM, TE, TF,
                                              fc2_b, out, gamma3, out, nullptr, TE);
}